// round 2
// baseline (speedup 1.0000x reference)
#include <cuda_runtime.h>
#include <math.h>

#define NN 20480
#define EE 327680
#define GG 64
#define HD 256     // H*D
#define HH 4
#define DD 64
#define CC 10
#define NPG (NN/GG)   // 320 nodes per graph

// ---------------- scratch (static device globals; no allocation) ----------------
__device__ float  g_z [NN*HD];
__device__ float  g_hA[NN*HD];
__device__ float  g_hB[NN*HD];
__device__ float  g_el[NN*HH];
__device__ float  g_er[NN*HH];
__device__ int    g_deg[NN];
__device__ int    g_rowptr[NN+1];
__device__ int    g_cursor[NN];
__device__ int    g_esrc[EE];
__device__ float2 g_bp[128*HD];   // k-paired B: [K/2][256]

__device__ __forceinline__ float lrelu(float x) { return x > 0.f ? x : 0.2f * x; }
__device__ __forceinline__ float elu1 (float x) { return x > 0.f ? x : expm1f(x); }

// ---------------- CSR build ----------------
__global__ void zero_deg_kernel() {
    int i = blockIdx.x * blockDim.x + threadIdx.x;
    if (i < NN) g_deg[i] = 0;
}

__global__ void hist_kernel(const int* __restrict__ dst) {
    int i = blockIdx.x * blockDim.x + threadIdx.x;
    if (i < EE) atomicAdd(&g_deg[dst[i]], 1);
}

__global__ void scan_kernel() {   // one block, 512 threads, NN = 512*40
    __shared__ int part[512];
    const int CH = NN / 512;
    int t = threadIdx.x;
    int s = 0;
    for (int i = 0; i < CH; i++) s += g_deg[t*CH + i];
    part[t] = s;
    __syncthreads();
    if (t == 0) {
        int r = 0;
        for (int i = 0; i < 512; i++) { int v = part[i]; part[i] = r; r += v; }
        g_rowptr[NN] = r;
    }
    __syncthreads();
    int run = part[t];
    for (int i = 0; i < CH; i++) {
        int idx = t*CH + i;
        g_rowptr[idx] = run;
        g_cursor[idx] = run;
        run += g_deg[idx];
    }
}

__global__ void scatter_kernel(const int* __restrict__ src, const int* __restrict__ dst) {
    int i = blockIdx.x * blockDim.x + threadIdx.x;
    if (i < EE) {
        int p = atomicAdd(&g_cursor[dst[i]], 1);
        g_esrc[p] = src[i];
    }
}

// ---------------- pack B into k-pair layout: g_bp[k2][n] = (B[2k2][n], B[2k2+1][n]) ----------------
__global__ void bpack_kernel(const float* __restrict__ B, int K) {
    int i = blockIdx.x * blockDim.x + threadIdx.x;   // over (K/2)*256
    if (i < (K >> 1) * HD) {
        int k2 = i >> 8, n = i & 255;
        g_bp[i] = make_float2(B[(2*k2) * HD + n], B[(2*k2 + 1) * HD + n]);
    }
}

// ---------------- GEMM: C[M,256] = A[M,K] @ B[K,256], packed f32x2 along K ----------------
// 128x64 tile, 256 threads, per-thread 8 rows x 4 cols, acc packed (k even/odd halves).
__global__ __launch_bounds__(256, 2) void gemm2_kernel(const float* __restrict__ A,
                                                       float* __restrict__ C,
                                                       int K) {
    __shared__ float2 As[8][128];   // As[k2][m] = (A[m][2k2], A[m][2k2+1]) within chunk
    __shared__ float2 Bs[8][64];

    int tid  = threadIdx.x;
    int bm   = blockIdx.x * 128;
    int bn   = blockIdx.y * 64;
    int col0 = (tid & 15) * 4;
    int row0 = (tid >> 4) * 8;

    unsigned long long acc[8][4];
#pragma unroll
    for (int i = 0; i < 8; i++)
#pragma unroll
        for (int j = 0; j < 4; j++) acc[i][j] = 0ull;

    int a_row = tid >> 1;
    int a_k   = (tid & 1) * 8;      // k offset within chunk
    int b_k2  = tid >> 5;           // 0..7
    int b_n   = (tid & 31) * 2;     // 0..62

    const float*  aptr = A + (size_t)(bm + a_row) * K + a_k;
    const float2* bptr = g_bp + (size_t)b_k2 * HD + bn + b_n;

    float4 av0 = *(const float4*)(aptr);
    float4 av1 = *(const float4*)(aptr + 4);
    float4 bv  = *(const float4*)(bptr);

    int nchunk = K >> 4;
    for (int c = 0; c < nchunk; c++) {
        int p = a_k >> 1;
        As[p+0][a_row] = make_float2(av0.x, av0.y);
        As[p+1][a_row] = make_float2(av0.z, av0.w);
        As[p+2][a_row] = make_float2(av1.x, av1.y);
        As[p+3][a_row] = make_float2(av1.z, av1.w);
        *(float4*)&Bs[b_k2][b_n] = bv;
        __syncthreads();

        if (c + 1 < nchunk) {       // prefetch next chunk while computing
            aptr += 16;
            bptr += 8 * HD;
            av0 = *(const float4*)(aptr);
            av1 = *(const float4*)(aptr + 4);
            bv  = *(const float4*)(bptr);
        }

#pragma unroll
        for (int k2 = 0; k2 < 8; k2++) {
            ulonglong2 a01 = *(const ulonglong2*)&As[k2][row0];
            ulonglong2 a23 = *(const ulonglong2*)&As[k2][row0 + 2];
            ulonglong2 a45 = *(const ulonglong2*)&As[k2][row0 + 4];
            ulonglong2 a67 = *(const ulonglong2*)&As[k2][row0 + 6];
            ulonglong2 b01 = *(const ulonglong2*)&Bs[k2][col0];
            ulonglong2 b23 = *(const ulonglong2*)&Bs[k2][col0 + 2];
            unsigned long long ar[8] = {a01.x, a01.y, a23.x, a23.y,
                                        a45.x, a45.y, a67.x, a67.y};
            unsigned long long br[4] = {b01.x, b01.y, b23.x, b23.y};
#pragma unroll
            for (int i = 0; i < 8; i++)
#pragma unroll
                for (int j = 0; j < 4; j++)
                    asm("fma.rn.f32x2 %0, %1, %2, %0;"
                        : "+l"(acc[i][j]) : "l"(ar[i]), "l"(br[j]));
        }
        __syncthreads();
    }

#pragma unroll
    for (int i = 0; i < 8; i++) {
        float o[4];
#pragma unroll
        for (int j = 0; j < 4; j++) {
            float2 f = *(float2*)&acc[i][j];
            o[j] = f.x + f.y;       // reduce even-k / odd-k halves
        }
        float4 v = {o[0], o[1], o[2], o[3]};
        *(float4*)(C + (size_t)(bm + row0 + i) * HD + bn + col0) = v;
    }
}

// ---------------- attention projections: el/er [N,H] ----------------
__global__ void attn_kernel(const float* __restrict__ z,
                            const float* __restrict__ al,
                            const float* __restrict__ ar) {
    int gw   = (blockIdx.x * blockDim.x + threadIdx.x) >> 5;
    int lane = threadIdx.x & 31;
    if (gw >= NN) return;
    int hh = lane >> 3;
    int db = (lane & 7) * 8;

    const float4* zp = (const float4*)(z + (size_t)gw * HD + lane * 8);
    float4 z0 = zp[0], z1 = zp[1];
    const float4* ap = (const float4*)(al + hh * DD + db);
    float4 a0 = ap[0], a1 = ap[1];
    const float4* rp = (const float4*)(ar + hh * DD + db);
    float4 r0 = rp[0], r1 = rp[1];

    float dl = z0.x*a0.x + z0.y*a0.y + z0.z*a0.z + z0.w*a0.w
             + z1.x*a1.x + z1.y*a1.y + z1.z*a1.z + z1.w*a1.w;
    float dr = z0.x*r0.x + z0.y*r0.y + z0.z*r0.z + z0.w*r0.w
             + z1.x*r1.x + z1.y*r1.y + z1.z*r1.z + z1.w*r1.w;
#pragma unroll
    for (int o = 4; o >= 1; o >>= 1) {
        dl += __shfl_xor_sync(0xffffffffu, dl, o);
        dr += __shfl_xor_sync(0xffffffffu, dr, o);
    }
    if ((lane & 7) == 0) {
        g_el[gw * HH + hh] = dl;
        g_er[gw * HH + hh] = dr;
    }
}

// ---------------- per-node edge-softmax aggregation (warp per node) ----------------
__global__ __launch_bounds__(256) void agg_kernel(const float* __restrict__ z,
                                                  const float* __restrict__ hprev,
                                                  float* __restrict__ hout,
                                                  int residual) {
    int n    = (blockIdx.x * blockDim.x + threadIdx.x) >> 5;
    int lane = threadIdx.x & 31;
    if (n >= NN) return;

    int base = g_rowptr[n];
    int deg  = g_rowptr[n + 1] - base;
    float4 er4 = ((const float4*)g_er)[n];

    // pass A: per-head max of leaky(el[src]+er[n])
    float m0 = -1e30f, m1 = -1e30f, m2 = -1e30f, m3 = -1e30f;
    for (int k = lane; k < deg; k += 32) {
        int s = g_esrc[base + k];
        float4 e4 = ((const float4*)g_el)[s];
        m0 = fmaxf(m0, lrelu(e4.x + er4.x));
        m1 = fmaxf(m1, lrelu(e4.y + er4.y));
        m2 = fmaxf(m2, lrelu(e4.z + er4.z));
        m3 = fmaxf(m3, lrelu(e4.w + er4.w));
    }
#pragma unroll
    for (int o = 16; o >= 1; o >>= 1) {
        m0 = fmaxf(m0, __shfl_xor_sync(0xffffffffu, m0, o));
        m1 = fmaxf(m1, __shfl_xor_sync(0xffffffffu, m1, o));
        m2 = fmaxf(m2, __shfl_xor_sync(0xffffffffu, m2, o));
        m3 = fmaxf(m3, __shfl_xor_sync(0xffffffffu, m3, o));
    }

    int hh = lane >> 3;   // lane owns features lane*8..lane*8+7 -> head = lane/8

    float acc0 = 0.f, acc1 = 0.f, acc2 = 0.f, acc3 = 0.f;
    float acc4 = 0.f, acc5 = 0.f, acc6 = 0.f, acc7 = 0.f;
    float ssum = 0.f;

    for (int c = 0; c < deg; c += 32) {
        int rem = deg - c; if (rem > 32) rem = 32;
        int    s_l = 0;
        float4 w4  = {0.f, 0.f, 0.f, 0.f};
        if (lane < rem) {
            s_l = g_esrc[base + c + lane];
            float4 e4 = ((const float4*)g_el)[s_l];
            w4.x = __expf(lrelu(e4.x + er4.x) - m0);
            w4.y = __expf(lrelu(e4.y + er4.y) - m1);
            w4.z = __expf(lrelu(e4.z + er4.z) - m2);
            w4.w = __expf(lrelu(e4.w + er4.w) - m3);
        }
        for (int k = 0; k < rem; k++) {
            int   s  = __shfl_sync(0xffffffffu, s_l, k);
            float wx = __shfl_sync(0xffffffffu, w4.x, k);
            float wy = __shfl_sync(0xffffffffu, w4.y, k);
            float wz = __shfl_sync(0xffffffffu, w4.z, k);
            float ww = __shfl_sync(0xffffffffu, w4.w, k);
            float w  = (hh == 0) ? wx : (hh == 1) ? wy : (hh == 2) ? wz : ww;
            ssum += w;
            const float4* zr = (const float4*)(z + (size_t)s * HD + lane * 8);
            float4 a = zr[0], b = zr[1];
            acc0 = fmaf(w, a.x, acc0); acc1 = fmaf(w, a.y, acc1);
            acc2 = fmaf(w, a.z, acc2); acc3 = fmaf(w, a.w, acc3);
            acc4 = fmaf(w, b.x, acc4); acc5 = fmaf(w, b.y, acc5);
            acc6 = fmaf(w, b.z, acc6); acc7 = fmaf(w, b.w, acc7);
        }
    }

    float inv = 1.f / ssum;   // deg >= 1 guaranteed -> ssum > 0
    float o8[8] = {acc0*inv, acc1*inv, acc2*inv, acc3*inv,
                   acc4*inv, acc5*inv, acc6*inv, acc7*inv};
    size_t ob = (size_t)n * HD + lane * 8;
    if (residual) {
        const float4* pp = (const float4*)(hprev + ob);
        float4 p0 = pp[0], p1 = pp[1];
        float pr[8] = {p0.x, p0.y, p0.z, p0.w, p1.x, p1.y, p1.z, p1.w};
#pragma unroll
        for (int i = 0; i < 8; i++) o8[i] = elu1(o8[i] + pr[i]);  // GATConv-internal ELU
    }
#pragma unroll
    for (int i = 0; i < 8; i++) o8[i] = elu1(o8[i]);              // model-level ELU
    float4 v0 = {o8[0], o8[1], o8[2], o8[3]};
    float4 v1 = {o8[4], o8[5], o8[6], o8[7]};
    *(float4*)(hout + ob)     = v0;
    *(float4*)(hout + ob + 4) = v1;
}

// ---------------- pooling + classifier ----------------
__global__ __launch_bounds__(256) void pool_kernel(const float* __restrict__ h,
                                                   const float* __restrict__ Wc,
                                                   const float* __restrict__ bc,
                                                   float* __restrict__ out) {
    __shared__ float hg[HD];
    int g = blockIdx.x;
    int t = threadIdx.x;
    float s = 0.f;
    const float* base = h + (size_t)g * NPG * HD + t;
    for (int i = 0; i < NPG; i++) s += base[(size_t)i * HD];
    hg[t] = elu1(s * (1.f / NPG));
    __syncthreads();
    if (t < CC) {
        float acc = bc[t];
        for (int f = 0; f < HD; f++) acc = fmaf(hg[f], Wc[f * CC + t], acc);
        out[g * CC + t] = acc;
    }
}

// ---------------- launch ----------------
extern "C" void kernel_launch(void* const* d_in, const int* in_sizes, int n_in,
                              void* d_out, int out_size) {
    const float* x   = (const float*)d_in[0];
    const int*   src = (const int*)  d_in[1];
    const int*   dst = (const int*)  d_in[2];
    const float* W0  = (const float*)d_in[4];
    const float* al0 = (const float*)d_in[5];
    const float* ar0 = (const float*)d_in[6];
    const float* W1  = (const float*)d_in[7];
    const float* al1 = (const float*)d_in[8];
    const float* ar1 = (const float*)d_in[9];
    const float* W2  = (const float*)d_in[10];
    const float* al2 = (const float*)d_in[11];
    const float* ar2 = (const float*)d_in[12];
    const float* Wc  = (const float*)d_in[13];
    const float* bc  = (const float*)d_in[14];
    float* out = (float*)d_out;

    float *z, *hA, *hB;
    cudaGetSymbolAddress((void**)&z,  g_z);
    cudaGetSymbolAddress((void**)&hA, g_hA);
    cudaGetSymbolAddress((void**)&hB, g_hB);

    // CSR by dst (deterministic work; intra-bucket order only perturbs fp sum order)
    zero_deg_kernel<<<(NN + 255) / 256, 256>>>();
    hist_kernel<<<(EE + 255) / 256, 256>>>(dst);
    scan_kernel<<<1, 512>>>();
    scatter_kernel<<<(EE + 255) / 256, 256>>>(src, dst);

    dim3 ggrid(NN / 128, HD / 64);

    // layer 0 (no residual)
    bpack_kernel<<<(64 * HD + 255) / 256, 256>>>(W0, 128);
    gemm2_kernel<<<ggrid, 256>>>(x, z, 128);
    attn_kernel<<<NN / 8, 256>>>(z, al0, ar0);
    agg_kernel<<<NN / 8, 256>>>(z, nullptr, hA, 0);

    // layer 1 (residual)
    bpack_kernel<<<(128 * HD + 255) / 256, 256>>>(W1, 256);
    gemm2_kernel<<<ggrid, 256>>>(hA, z, 256);
    attn_kernel<<<NN / 8, 256>>>(z, al1, ar1);
    agg_kernel<<<NN / 8, 256>>>(z, hA, hB, 1);

    // layer 2 (residual)
    bpack_kernel<<<(128 * HD + 255) / 256, 256>>>(W2, 256);
    gemm2_kernel<<<ggrid, 256>>>(hB, z, 256);
    attn_kernel<<<NN / 8, 256>>>(z, al2, ar2);
    agg_kernel<<<NN / 8, 256>>>(z, hB, hA, 1);

    pool_kernel<<<GG, 256>>>(hA, Wc, bc, out);
}

// round 4
// speedup vs baseline: 1.3854x; 1.3854x over previous
#include <cuda_runtime.h>
#include <cuda_bf16.h>
#include <math.h>
#include <stdint.h>

#define NN 20480
#define EE 327680
#define GG 64
#define HD 256     // H*D
#define HH 4
#define DD 64
#define CC 10
#define NPG (NN/GG)

// ---------------- scratch (static device globals; no allocation) ----------------
__device__ float g_z [NN*HD];
__device__ float g_hA[NN*HD];
__device__ float g_hB[NN*HD];
__device__ float g_el[NN*HH];
__device__ float g_er[NN*HH];
__device__ int   g_deg[NN];
__device__ int   g_rowptr[NN+1];
__device__ int   g_cursor[NN];
__device__ int   g_esrc[EE];
__device__ __nv_bfloat16 g_ahi[NN*HD];      // A split (per-layer reuse)
__device__ __nv_bfloat16 g_alo[NN*HD];
__device__ __nv_bfloat16 g_bhi[3][HD*HD];   // B split per layer: [K][256]
__device__ __nv_bfloat16 g_blo[3][HD*HD];

__device__ __forceinline__ float lrelu(float x) { return x > 0.f ? x : 0.2f * x; }
__device__ __forceinline__ float elu1 (float x) { return x > 0.f ? x : expm1f(x); }

__device__ __forceinline__ uint32_t smem_u32(const void* p) {
    uint32_t a;
    asm("{ .reg .u64 t; cvta.to.shared.u64 t, %1; cvt.u32.u64 %0, t; }" : "=r"(a) : "l"(p));
    return a;
}
__device__ __forceinline__ void ldmat4(uint32_t* r, uint32_t a) {
    asm volatile("ldmatrix.sync.aligned.m8n8.x4.shared.b16 {%0,%1,%2,%3}, [%4];"
        : "=r"(r[0]), "=r"(r[1]), "=r"(r[2]), "=r"(r[3]) : "r"(a));
}
__device__ __forceinline__ void ldmat4t(uint32_t* r, uint32_t a) {
    asm volatile("ldmatrix.sync.aligned.m8n8.x4.trans.shared.b16 {%0,%1,%2,%3}, [%4];"
        : "=r"(r[0]), "=r"(r[1]), "=r"(r[2]), "=r"(r[3]) : "r"(a));
}
__device__ __forceinline__ void mma16816(float* c, const uint32_t* a, const uint32_t* b) {
    asm volatile(
        "mma.sync.aligned.m16n8k16.row.col.f32.bf16.bf16.f32 "
        "{%0,%1,%2,%3}, {%4,%5,%6,%7}, {%8,%9}, {%0,%1,%2,%3};"
        : "+f"(c[0]), "+f"(c[1]), "+f"(c[2]), "+f"(c[3])
        : "r"(a[0]), "r"(a[1]), "r"(a[2]), "r"(a[3]), "r"(b[0]), "r"(b[1]));
}
#define CP16(s, g) asm volatile("cp.async.cg.shared.global [%0], [%1], 16;" \
    :: "r"(s), "l"(__cvta_generic_to_global(g)))
#define CP_COMMIT() asm volatile("cp.async.commit_group;" ::: "memory")
#define CP_WAIT0()  asm volatile("cp.async.wait_group 0;" ::: "memory")
#define CP_WAIT1()  asm volatile("cp.async.wait_group 1;" ::: "memory")

// ---------------- CSR build ----------------
__global__ void zero_deg_kernel() {
    int i = blockIdx.x * blockDim.x + threadIdx.x;
    if (i < NN) g_deg[i] = 0;
}
__global__ void hist_kernel(const int* __restrict__ dst) {
    int i = blockIdx.x * blockDim.x + threadIdx.x;
    if (i < EE) atomicAdd(&g_deg[dst[i]], 1);
}
__global__ void scan_kernel() {
    __shared__ int part[512];
    const int CH = NN / 512;
    int t = threadIdx.x;
    int s = 0;
    for (int i = 0; i < CH; i++) s += g_deg[t*CH + i];
    part[t] = s;
    __syncthreads();
    if (t == 0) {
        int r = 0;
        for (int i = 0; i < 512; i++) { int v = part[i]; part[i] = r; r += v; }
        g_rowptr[NN] = r;
    }
    __syncthreads();
    int run = part[t];
    for (int i = 0; i < CH; i++) {
        int idx = t*CH + i;
        g_rowptr[idx] = run;
        g_cursor[idx] = run;
        run += g_deg[idx];
    }
}
__global__ void scatter_kernel(const int* __restrict__ src, const int* __restrict__ dst) {
    int i = blockIdx.x * blockDim.x + threadIdx.x;
    if (i < EE) {
        int p = atomicAdd(&g_cursor[dst[i]], 1);
        g_esrc[p] = src[i];
    }
}

// ---------------- fp32 -> bf16 hi/lo split ----------------
__global__ void convA_kernel(const float* __restrict__ A, int n4) {
    int i = blockIdx.x * blockDim.x + threadIdx.x;
    if (i >= n4) return;
    float4 v = ((const float4*)A)[i];
    __nv_bfloat16 hx = __float2bfloat16(v.x), hy = __float2bfloat16(v.y);
    __nv_bfloat16 hz = __float2bfloat16(v.z), hw = __float2bfloat16(v.w);
    __nv_bfloat16 lx = __float2bfloat16(v.x - __bfloat162float(hx));
    __nv_bfloat16 ly = __float2bfloat16(v.y - __bfloat162float(hy));
    __nv_bfloat16 lz = __float2bfloat16(v.z - __bfloat162float(hz));
    __nv_bfloat16 lw = __float2bfloat16(v.w - __bfloat162float(hw));
    ((__nv_bfloat162*)g_ahi)[2*i]   = __nv_bfloat162(hx, hy);
    ((__nv_bfloat162*)g_ahi)[2*i+1] = __nv_bfloat162(hz, hw);
    ((__nv_bfloat162*)g_alo)[2*i]   = __nv_bfloat162(lx, ly);
    ((__nv_bfloat162*)g_alo)[2*i+1] = __nv_bfloat162(lz, lw);
}
__global__ void convB_kernel(const float* __restrict__ B, int n, int layer) {
    int i = blockIdx.x * blockDim.x + threadIdx.x;   // over K*256
    if (i >= n) return;
    float v = B[i];
    __nv_bfloat16 h = __float2bfloat16(v);
    g_bhi[layer][i] = h;
    g_blo[layer][i] = __float2bfloat16(v - __bfloat162float(h));
}

// ---------------- mma.sync GEMM: C[NN,256] = A[NN,K] @ B[K,256], bf16 hi/lo ----------------
// CTA 128(M)x128(N), 8 warps (warp = 32x64), K chunks of 32, cp.async double buffer.
#define ARB 80        // A smem row bytes (32 bf16 + pad)
#define BRB 272       // B smem row bytes (128 bf16 + pad)
#define S_ALO 10240
#define S_BHI 20480
#define S_BLO 29184
#define BUF   37888
#define SMEM_GEMM (2*BUF)

__global__ __launch_bounds__(256, 1) void gemm_mma_kernel(
    const __nv_bfloat16* __restrict__ Ahi, const __nv_bfloat16* __restrict__ Alo,
    const __nv_bfloat16* __restrict__ Bhi, const __nv_bfloat16* __restrict__ Blo,
    float* __restrict__ C, int K) {
    extern __shared__ char sm[];
    uint32_t sb = smem_u32(sm);
    int tid = threadIdx.x, lane = tid & 31, wid = tid >> 5;
    int wm = wid & 3, wn = wid >> 2;
    int bm = blockIdx.x * 128, bn = blockIdx.y * 128;

    float acc[2][8][4];
#pragma unroll
    for (int i = 0; i < 2; i++)
#pragma unroll
        for (int j = 0; j < 8; j++)
#pragma unroll
            for (int q = 0; q < 4; q++) acc[i][j][q] = 0.f;

    auto issue = [&](int c, int buf) {
        int k0 = c * 32;
        uint32_t s0 = sb + buf * BUF;
#pragma unroll
        for (int r = 0; r < 2; r++) {
            int idx  = tid + r * 256;
            int arow = idx >> 2, ach = idx & 3;          // A: 128 rows x 4 chunks
            const __nv_bfloat16* gh = Ahi + (size_t)(bm + arow) * K + k0 + ach * 8;
            const __nv_bfloat16* gl = Alo + (size_t)(bm + arow) * K + k0 + ach * 8;
            CP16(s0 + arow * ARB + ach * 16, gh);
            CP16(s0 + S_ALO + arow * ARB + ach * 16, gl);
            int brow = idx >> 4, bch = idx & 15;         // B: 32 rows x 16 chunks
            const __nv_bfloat16* bh = Bhi + (size_t)(k0 + brow) * HD + bn + bch * 8;
            const __nv_bfloat16* bl = Blo + (size_t)(k0 + brow) * HD + bn + bch * 8;
            CP16(s0 + S_BHI + brow * BRB + bch * 16, bh);
            CP16(s0 + S_BLO + brow * BRB + bch * 16, bl);
        }
    };

    auto compute = [&](int buf) {
        uint32_t s0 = sb + buf * BUF;
#pragma unroll
        for (int ks = 0; ks < 32; ks += 16) {
            uint32_t ah[2][4], al[2][4];
#pragma unroll
            for (int i = 0; i < 2; i++) {
                int row = wm * 32 + i * 16 + (lane & 15);
                uint32_t ad = s0 + row * ARB + (ks + (lane >> 4) * 8) * 2;
                ldmat4(ah[i], ad);
                ldmat4(al[i], ad + S_ALO);
            }
#pragma unroll
            for (int jj = 0; jj < 4; jj++) {
                int krow = ks + (lane & 15);
                int ncol = wn * 64 + jj * 16 + (lane >> 4) * 8;
                uint32_t bd = s0 + S_BHI + krow * BRB + ncol * 2;
                uint32_t bh[4], bl[4];
                ldmat4t(bh, bd);
                ldmat4t(bl, bd + (S_BLO - S_BHI));
#pragma unroll
                for (int i = 0; i < 2; i++) {
                    mma16816(acc[i][2*jj],   ah[i], bh);
                    mma16816(acc[i][2*jj],   al[i], bh);
                    mma16816(acc[i][2*jj],   ah[i], bl);
                    mma16816(acc[i][2*jj+1], ah[i], bh + 2);
                    mma16816(acc[i][2*jj+1], al[i], bh + 2);
                    mma16816(acc[i][2*jj+1], ah[i], bl + 2);
                }
            }
        }
    };

    int nch = K >> 5;
    issue(0, 0);
    CP_COMMIT();
    for (int c = 0; c < nch; c++) {
        if (c + 1 < nch) {
            issue(c + 1, (c + 1) & 1);
            CP_COMMIT();
            CP_WAIT1();
        } else {
            CP_WAIT0();
        }
        __syncthreads();
        compute(c & 1);
        __syncthreads();   // all reads of this buffer done before it is re-filled
    }

    int grp = lane >> 2, tig = lane & 3;
#pragma unroll
    for (int i = 0; i < 2; i++) {
        int rbase = bm + wm * 32 + i * 16 + grp;
#pragma unroll
        for (int j = 0; j < 8; j++) {
            int col = bn + wn * 64 + j * 8 + tig * 2;
            float2 v0 = {acc[i][j][0], acc[i][j][1]};
            float2 v1 = {acc[i][j][2], acc[i][j][3]};
            *(float2*)(C + (size_t)rbase * HD + col)       = v0;
            *(float2*)(C + (size_t)(rbase + 8) * HD + col) = v1;
        }
    }
}

// ---------------- attention projections: el/er [N,H] ----------------
__global__ void attn_kernel(const float* __restrict__ z,
                            const float* __restrict__ al,
                            const float* __restrict__ ar) {
    int gw   = (blockIdx.x * blockDim.x + threadIdx.x) >> 5;
    int lane = threadIdx.x & 31;
    if (gw >= NN) return;
    int hh = lane >> 3;
    int db = (lane & 7) * 8;

    const float4* zp = (const float4*)(z + (size_t)gw * HD + lane * 8);
    float4 z0 = zp[0], z1 = zp[1];
    const float4* ap = (const float4*)(al + hh * DD + db);
    float4 a0 = ap[0], a1 = ap[1];
    const float4* rp = (const float4*)(ar + hh * DD + db);
    float4 r0 = rp[0], r1 = rp[1];

    float dl = z0.x*a0.x + z0.y*a0.y + z0.z*a0.z + z0.w*a0.w
             + z1.x*a1.x + z1.y*a1.y + z1.z*a1.z + z1.w*a1.w;
    float dr = z0.x*r0.x + z0.y*r0.y + z0.z*r0.z + z0.w*r0.w
             + z1.x*r1.x + z1.y*r1.y + z1.z*r1.z + z1.w*r1.w;
#pragma unroll
    for (int o = 4; o >= 1; o >>= 1) {
        dl += __shfl_xor_sync(0xffffffffu, dl, o);
        dr += __shfl_xor_sync(0xffffffffu, dr, o);
    }
    if ((lane & 7) == 0) {
        g_el[gw * HH + hh] = dl;
        g_er[gw * HH + hh] = dr;
    }
}

// ---------------- per-node edge-softmax aggregation (warp per node) ----------------
__global__ __launch_bounds__(256) void agg_kernel(const float* __restrict__ z,
                                                  const float* __restrict__ hprev,
                                                  float* __restrict__ hout,
                                                  int residual) {
    int n    = (blockIdx.x * blockDim.x + threadIdx.x) >> 5;
    int lane = threadIdx.x & 31;
    if (n >= NN) return;

    int base = g_rowptr[n];
    int deg  = g_rowptr[n + 1] - base;
    float4 er4 = ((const float4*)g_er)[n];

    float m0 = -1e30f, m1 = -1e30f, m2 = -1e30f, m3 = -1e30f;
    for (int k = lane; k < deg; k += 32) {
        int s = g_esrc[base + k];
        float4 e4 = ((const float4*)g_el)[s];
        m0 = fmaxf(m0, lrelu(e4.x + er4.x));
        m1 = fmaxf(m1, lrelu(e4.y + er4.y));
        m2 = fmaxf(m2, lrelu(e4.z + er4.z));
        m3 = fmaxf(m3, lrelu(e4.w + er4.w));
    }
#pragma unroll
    for (int o = 16; o >= 1; o >>= 1) {
        m0 = fmaxf(m0, __shfl_xor_sync(0xffffffffu, m0, o));
        m1 = fmaxf(m1, __shfl_xor_sync(0xffffffffu, m1, o));
        m2 = fmaxf(m2, __shfl_xor_sync(0xffffffffu, m2, o));
        m3 = fmaxf(m3, __shfl_xor_sync(0xffffffffu, m3, o));
    }

    int hh = lane >> 3;

    float acc0 = 0.f, acc1 = 0.f, acc2 = 0.f, acc3 = 0.f;
    float acc4 = 0.f, acc5 = 0.f, acc6 = 0.f, acc7 = 0.f;
    float ssum = 0.f;

    for (int c = 0; c < deg; c += 32) {
        int rem = deg - c; if (rem > 32) rem = 32;
        int    s_l = 0;
        float4 w4  = {0.f, 0.f, 0.f, 0.f};
        if (lane < rem) {
            s_l = g_esrc[base + c + lane];
            float4 e4 = ((const float4*)g_el)[s_l];
            w4.x = __expf(lrelu(e4.x + er4.x) - m0);
            w4.y = __expf(lrelu(e4.y + er4.y) - m1);
            w4.z = __expf(lrelu(e4.z + er4.z) - m2);
            w4.w = __expf(lrelu(e4.w + er4.w) - m3);
        }
        for (int k = 0; k < rem; k++) {
            int   s  = __shfl_sync(0xffffffffu, s_l, k);
            float wx = __shfl_sync(0xffffffffu, w4.x, k);
            float wy = __shfl_sync(0xffffffffu, w4.y, k);
            float wz = __shfl_sync(0xffffffffu, w4.z, k);
            float ww = __shfl_sync(0xffffffffu, w4.w, k);
            float w  = (hh == 0) ? wx : (hh == 1) ? wy : (hh == 2) ? wz : ww;
            ssum += w;
            const float4* zr = (const float4*)(z + (size_t)s * HD + lane * 8);
            float4 a = zr[0], b = zr[1];
            acc0 = fmaf(w, a.x, acc0); acc1 = fmaf(w, a.y, acc1);
            acc2 = fmaf(w, a.z, acc2); acc3 = fmaf(w, a.w, acc3);
            acc4 = fmaf(w, b.x, acc4); acc5 = fmaf(w, b.y, acc5);
            acc6 = fmaf(w, b.z, acc6); acc7 = fmaf(w, b.w, acc7);
        }
    }

    float inv = 1.f / ssum;
    float o8[8] = {acc0*inv, acc1*inv, acc2*inv, acc3*inv,
                   acc4*inv, acc5*inv, acc6*inv, acc7*inv};
    size_t ob = (size_t)n * HD + lane * 8;
    if (residual) {
        const float4* pp = (const float4*)(hprev + ob);
        float4 p0 = pp[0], p1 = pp[1];
        float pr[8] = {p0.x, p0.y, p0.z, p0.w, p1.x, p1.y, p1.z, p1.w};
#pragma unroll
        for (int i = 0; i < 8; i++) o8[i] = elu1(o8[i] + pr[i]);
    }
#pragma unroll
    for (int i = 0; i < 8; i++) o8[i] = elu1(o8[i]);
    float4 v0 = {o8[0], o8[1], o8[2], o8[3]};
    float4 v1 = {o8[4], o8[5], o8[6], o8[7]};
    *(float4*)(hout + ob)     = v0;
    *(float4*)(hout + ob + 4) = v1;
}

// ---------------- pooling + classifier ----------------
__global__ __launch_bounds__(256) void pool_kernel(const float* __restrict__ h,
                                                   const float* __restrict__ Wc,
                                                   const float* __restrict__ bc,
                                                   float* __restrict__ out) {
    __shared__ float hg[HD];
    int g = blockIdx.x;
    int t = threadIdx.x;
    float s = 0.f;
    const float* base = h + (size_t)g * NPG * HD + t;
    for (int i = 0; i < NPG; i++) s += base[(size_t)i * HD];
    hg[t] = elu1(s * (1.f / NPG));
    __syncthreads();
    if (t < CC) {
        float acc = bc[t];
        for (int f = 0; f < HD; f++) acc = fmaf(hg[f], Wc[f * CC + t], acc);
        out[g * CC + t] = acc;
    }
}

// ---------------- launch ----------------
extern "C" void kernel_launch(void* const* d_in, const int* in_sizes, int n_in,
                              void* d_out, int out_size) {
    const float* x   = (const float*)d_in[0];
    const int*   src = (const int*)  d_in[1];
    const int*   dst = (const int*)  d_in[2];
    const float* W0  = (const float*)d_in[4];
    const float* al0 = (const float*)d_in[5];
    const float* ar0 = (const float*)d_in[6];
    const float* W1  = (const float*)d_in[7];
    const float* al1 = (const float*)d_in[8];
    const float* ar1 = (const float*)d_in[9];
    const float* W2  = (const float*)d_in[10];
    const float* al2 = (const float*)d_in[11];
    const float* ar2 = (const float*)d_in[12];
    const float* Wc  = (const float*)d_in[13];
    const float* bc  = (const float*)d_in[14];
    float* out = (float*)d_out;

    float *z, *hA, *hB;
    __nv_bfloat16 *ahi, *alo, *bhi, *blo;
    cudaGetSymbolAddress((void**)&z,   g_z);
    cudaGetSymbolAddress((void**)&hA,  g_hA);
    cudaGetSymbolAddress((void**)&hB,  g_hB);
    cudaGetSymbolAddress((void**)&ahi, g_ahi);
    cudaGetSymbolAddress((void**)&alo, g_alo);
    cudaGetSymbolAddress((void**)&bhi, g_bhi);
    cudaGetSymbolAddress((void**)&blo, g_blo);

    cudaFuncSetAttribute(gemm_mma_kernel,
                         cudaFuncAttributeMaxDynamicSharedMemorySize, SMEM_GEMM);

    // CSR by dst
    zero_deg_kernel<<<(NN + 255) / 256, 256>>>();
    hist_kernel<<<(EE + 255) / 256, 256>>>(dst);
    scan_kernel<<<1, 512>>>();
    scatter_kernel<<<(EE + 255) / 256, 256>>>(src, dst);

    // weight conversions
    convB_kernel<<<(128 * HD + 255) / 256, 256>>>(W0, 128 * HD, 0);
    convB_kernel<<<(256 * HD + 255) / 256, 256>>>(W1, 256 * HD, 1);
    convB_kernel<<<(256 * HD + 255) / 256, 256>>>(W2, 256 * HD, 2);

    dim3 ggrid(NN / 128, 2);

    // layer 0 (K=128, no residual)
    convA_kernel<<<(NN * 128 / 4 + 255) / 256, 256>>>(x, NN * 128 / 4);
    gemm_mma_kernel<<<ggrid, 256, SMEM_GEMM>>>(ahi, alo, bhi, blo, z, 128);
    attn_kernel<<<NN / 8, 256>>>(z, al0, ar0);
    agg_kernel<<<NN / 8, 256>>>(z, nullptr, hA, 0);

    // layer 1 (K=256, residual)
    convA_kernel<<<(NN * 256 / 4 + 255) / 256, 256>>>(hA, NN * 256 / 4);
    gemm_mma_kernel<<<ggrid, 256, SMEM_GEMM>>>(ahi, alo, bhi + HD * HD,
                                               blo + HD * HD, z, 256);
    attn_kernel<<<NN / 8, 256>>>(z, al1, ar1);
    agg_kernel<<<NN / 8, 256>>>(z, hA, hB, 1);

    // layer 2 (K=256, residual)
    convA_kernel<<<(NN * 256 / 4 + 255) / 256, 256>>>(hB, NN * 256 / 4);
    gemm_mma_kernel<<<ggrid, 256, SMEM_GEMM>>>(ahi, alo, bhi + 2 * HD * HD,
                                               blo + 2 * HD * HD, z, 256);
    attn_kernel<<<NN / 8, 256>>>(z, al2, ar2);
    agg_kernel<<<NN / 8, 256>>>(z, hB, hA, 1);

    pool_kernel<<<GG, 256>>>(hA, Wc, bc, out);
}

// round 5
// speedup vs baseline: 1.5503x; 1.1190x over previous
#include <cuda_runtime.h>
#include <cuda_bf16.h>
#include <math.h>
#include <stdint.h>

#define NN 20480
#define EE 327680
#define GG 64
#define HD 256     // H*D
#define HH 4
#define DD 64
#define CC 10
#define NPG (NN/GG)

// ---------------- scratch (static device globals; no allocation) ----------------
__device__ float g_z [NN*HD];
__device__ float g_hA[NN*HD];
__device__ float g_hB[NN*HD];
__device__ float g_el[NN*HH];
__device__ float g_er[NN*HH];
__device__ int   g_deg[NN];
__device__ int   g_rowptr[NN+1];
__device__ int   g_cursor[NN];
__device__ int   g_esrc[EE];
__device__ __nv_bfloat16 g_ahi[NN*HD];      // A split (per-layer reuse)
__device__ __nv_bfloat16 g_alo[NN*HD];
__device__ __nv_bfloat16 g_bhi[3][HD*HD];   // B split per layer: [K][256]
__device__ __nv_bfloat16 g_blo[3][HD*HD];

__device__ __forceinline__ float lrelu(float x) { return x > 0.f ? x : 0.2f * x; }
__device__ __forceinline__ float elu1 (float x) { return x > 0.f ? x : expm1f(x); }

__device__ __forceinline__ uint32_t smem_u32(const void* p) {
    uint32_t a;
    asm("{ .reg .u64 t; cvta.to.shared.u64 t, %1; cvt.u32.u64 %0, t; }" : "=r"(a) : "l"(p));
    return a;
}
__device__ __forceinline__ void ldmat4(uint32_t* r, uint32_t a) {
    asm volatile("ldmatrix.sync.aligned.m8n8.x4.shared.b16 {%0,%1,%2,%3}, [%4];"
        : "=r"(r[0]), "=r"(r[1]), "=r"(r[2]), "=r"(r[3]) : "r"(a));
}
__device__ __forceinline__ void ldmat4t(uint32_t* r, uint32_t a) {
    asm volatile("ldmatrix.sync.aligned.m8n8.x4.trans.shared.b16 {%0,%1,%2,%3}, [%4];"
        : "=r"(r[0]), "=r"(r[1]), "=r"(r[2]), "=r"(r[3]) : "r"(a));
}
__device__ __forceinline__ void mma16816(float* c, const uint32_t* a, const uint32_t* b) {
    asm volatile(
        "mma.sync.aligned.m16n8k16.row.col.f32.bf16.bf16.f32 "
        "{%0,%1,%2,%3}, {%4,%5,%6,%7}, {%8,%9}, {%0,%1,%2,%3};"
        : "+f"(c[0]), "+f"(c[1]), "+f"(c[2]), "+f"(c[3])
        : "r"(a[0]), "r"(a[1]), "r"(a[2]), "r"(a[3]), "r"(b[0]), "r"(b[1]));
}
#define CP16(s, g) asm volatile("cp.async.cg.shared.global [%0], [%1], 16;" \
    :: "r"(s), "l"(__cvta_generic_to_global(g)))
#define CP_COMMIT() asm volatile("cp.async.commit_group;" ::: "memory")
#define CP_WAIT0()  asm volatile("cp.async.wait_group 0;" ::: "memory")
#define CP_WAIT1()  asm volatile("cp.async.wait_group 1;" ::: "memory")

// ---------------- CSR build ----------------
__global__ void zero_deg_kernel() {
    int i = blockIdx.x * blockDim.x + threadIdx.x;
    if (i < NN) g_deg[i] = 0;
}
__global__ void hist_kernel(const int* __restrict__ dst) {
    int i = blockIdx.x * blockDim.x + threadIdx.x;
    if (i < EE) atomicAdd(&g_deg[dst[i]], 1);
}
__global__ void scan_kernel() {
    __shared__ int part[512];
    const int CH = NN / 512;
    int t = threadIdx.x;
    int s = 0;
    for (int i = 0; i < CH; i++) s += g_deg[t*CH + i];
    part[t] = s;
    __syncthreads();
    if (t == 0) {
        int r = 0;
        for (int i = 0; i < 512; i++) { int v = part[i]; part[i] = r; r += v; }
        g_rowptr[NN] = r;
    }
    __syncthreads();
    int run = part[t];
    for (int i = 0; i < CH; i++) {
        int idx = t*CH + i;
        g_rowptr[idx] = run;
        g_cursor[idx] = run;
        run += g_deg[idx];
    }
}
__global__ void scatter_kernel(const int* __restrict__ src, const int* __restrict__ dst) {
    int i = blockIdx.x * blockDim.x + threadIdx.x;
    if (i < EE) {
        int p = atomicAdd(&g_cursor[dst[i]], 1);
        g_esrc[p] = src[i];
    }
}

// ---------------- fp32 -> bf16 hi/lo split (layer-0 input only) ----------------
__global__ void convA_kernel(const float* __restrict__ A, int n4) {
    int i = blockIdx.x * blockDim.x + threadIdx.x;
    if (i >= n4) return;
    float4 v = ((const float4*)A)[i];
    __nv_bfloat16 hx = __float2bfloat16(v.x), hy = __float2bfloat16(v.y);
    __nv_bfloat16 hz = __float2bfloat16(v.z), hw = __float2bfloat16(v.w);
    __nv_bfloat16 lx = __float2bfloat16(v.x - __bfloat162float(hx));
    __nv_bfloat16 ly = __float2bfloat16(v.y - __bfloat162float(hy));
    __nv_bfloat16 lz = __float2bfloat16(v.z - __bfloat162float(hz));
    __nv_bfloat16 lw = __float2bfloat16(v.w - __bfloat162float(hw));
    ((__nv_bfloat162*)g_ahi)[2*i]   = __nv_bfloat162(hx, hy);
    ((__nv_bfloat162*)g_ahi)[2*i+1] = __nv_bfloat162(hz, hw);
    ((__nv_bfloat162*)g_alo)[2*i]   = __nv_bfloat162(lx, ly);
    ((__nv_bfloat162*)g_alo)[2*i+1] = __nv_bfloat162(lz, lw);
}
__global__ void convB_kernel(const float* __restrict__ B, int n, int layer) {
    int i = blockIdx.x * blockDim.x + threadIdx.x;
    if (i >= n) return;
    float v = B[i];
    __nv_bfloat16 h = __float2bfloat16(v);
    g_bhi[layer][i] = h;
    g_blo[layer][i] = __float2bfloat16(v - __bfloat162float(h));
}

// ---------------- mma.sync GEMM + fused attn projections ----------------
// CTA 128(M)x128(N), 8 warps (warp = 32x64), K chunks of 32, cp.async double buffer.
// Warp (wm,wn) at block-col bn owns exactly head (bn/64 + wn) -> computes el/er too.
#define ARB 80        // A smem row bytes (32 bf16 + pad)
#define BRB 272       // B smem row bytes (128 bf16 + pad)
#define S_ALO 10240
#define S_BHI 20480
#define S_BLO 29184
#define BUF   37888
#define SMEM_GEMM (2*BUF)

__global__ __launch_bounds__(256, 2) void gemm_mma_kernel(
    const __nv_bfloat16* __restrict__ Ahi, const __nv_bfloat16* __restrict__ Alo,
    const __nv_bfloat16* __restrict__ Bhi, const __nv_bfloat16* __restrict__ Blo,
    float* __restrict__ C,
    const float* __restrict__ al, const float* __restrict__ ar, int K) {
    extern __shared__ char sm[];
    uint32_t sb = smem_u32(sm);
    int tid = threadIdx.x, lane = tid & 31, wid = tid >> 5;
    int wm = wid & 3, wn = wid >> 2;
    int bm = blockIdx.x * 128, bn = blockIdx.y * 128;

    float acc[2][8][4];
#pragma unroll
    for (int i = 0; i < 2; i++)
#pragma unroll
        for (int j = 0; j < 8; j++)
#pragma unroll
            for (int q = 0; q < 4; q++) acc[i][j][q] = 0.f;

    auto issue = [&](int c, int buf) {
        int k0 = c * 32;
        uint32_t s0 = sb + buf * BUF;
#pragma unroll
        for (int r = 0; r < 2; r++) {
            int idx  = tid + r * 256;
            int arow = idx >> 2, ach = idx & 3;          // A: 128 rows x 4 chunks
            const __nv_bfloat16* gh = Ahi + (size_t)(bm + arow) * K + k0 + ach * 8;
            const __nv_bfloat16* gl = Alo + (size_t)(bm + arow) * K + k0 + ach * 8;
            CP16(s0 + arow * ARB + ach * 16, gh);
            CP16(s0 + S_ALO + arow * ARB + ach * 16, gl);
            int brow = idx >> 4, bch = idx & 15;         // B: 32 rows x 16 chunks
            const __nv_bfloat16* bh = Bhi + (size_t)(k0 + brow) * HD + bn + bch * 8;
            const __nv_bfloat16* bl = Blo + (size_t)(k0 + brow) * HD + bn + bch * 8;
            CP16(s0 + S_BHI + brow * BRB + bch * 16, bh);
            CP16(s0 + S_BLO + brow * BRB + bch * 16, bl);
        }
    };

    auto compute = [&](int buf) {
        uint32_t s0 = sb + buf * BUF;
#pragma unroll
        for (int ks = 0; ks < 32; ks += 16) {
            uint32_t ah[2][4], alr[2][4];
#pragma unroll
            for (int i = 0; i < 2; i++) {
                int row = wm * 32 + i * 16 + (lane & 15);
                uint32_t ad = s0 + row * ARB + (ks + (lane >> 4) * 8) * 2;
                ldmat4(ah[i], ad);
                ldmat4(alr[i], ad + S_ALO);
            }
#pragma unroll
            for (int jj = 0; jj < 4; jj++) {
                int krow = ks + (lane & 15);
                int ncol = wn * 64 + jj * 16 + (lane >> 4) * 8;
                uint32_t bd = s0 + S_BHI + krow * BRB + ncol * 2;
                uint32_t bh[4], bl[4];
                ldmat4t(bh, bd);
                ldmat4t(bl, bd + (S_BLO - S_BHI));
#pragma unroll
                for (int i = 0; i < 2; i++) {
                    mma16816(acc[i][2*jj],   ah[i],  bh);
                    mma16816(acc[i][2*jj],   alr[i], bh);
                    mma16816(acc[i][2*jj],   ah[i],  bl);
                    mma16816(acc[i][2*jj+1], ah[i],  bh + 2);
                    mma16816(acc[i][2*jj+1], alr[i], bh + 2);
                    mma16816(acc[i][2*jj+1], ah[i],  bl + 2);
                }
            }
        }
    };

    int nch = K >> 5;
    issue(0, 0);
    CP_COMMIT();
    for (int c = 0; c < nch; c++) {
        if (c + 1 < nch) {
            issue(c + 1, (c + 1) & 1);
            CP_COMMIT();
            CP_WAIT1();
        } else {
            CP_WAIT0();
        }
        __syncthreads();
        compute(c & 1);
        __syncthreads();
    }

    int grp = lane >> 2, tig = lane & 3;

    // ---- store z ----
#pragma unroll
    for (int i = 0; i < 2; i++) {
        int rbase = bm + wm * 32 + i * 16 + grp;
#pragma unroll
        for (int j = 0; j < 8; j++) {
            int col = bn + wn * 64 + j * 8 + tig * 2;
            float2 v0 = {acc[i][j][0], acc[i][j][1]};
            float2 v1 = {acc[i][j][2], acc[i][j][3]};
            *(float2*)(C + (size_t)rbase * HD + col)       = v0;
            *(float2*)(C + (size_t)(rbase + 8) * HD + col) = v1;
        }
    }

    // ---- fused attn projections: el/er for head hglob ----
    {
        int hglob = (bn >> 6) + wn;
        const float* alh = al + hglob * DD;
        const float* arh = ar + hglob * DD;
        float alv[16], arv[16];
#pragma unroll
        for (int j = 0; j < 8; j++) {
            int cw = j * 8 + tig * 2;
            alv[2*j]   = alh[cw];   alv[2*j+1] = alh[cw+1];
            arv[2*j]   = arh[cw];   arv[2*j+1] = arh[cw+1];
        }
#pragma unroll
        for (int i = 0; i < 2; i++) {
            float el1 = 0.f, er1 = 0.f, el2 = 0.f, er2 = 0.f;
#pragma unroll
            for (int j = 0; j < 8; j++) {
                el1 = fmaf(acc[i][j][0], alv[2*j], fmaf(acc[i][j][1], alv[2*j+1], el1));
                er1 = fmaf(acc[i][j][0], arv[2*j], fmaf(acc[i][j][1], arv[2*j+1], er1));
                el2 = fmaf(acc[i][j][2], alv[2*j], fmaf(acc[i][j][3], alv[2*j+1], el2));
                er2 = fmaf(acc[i][j][2], arv[2*j], fmaf(acc[i][j][3], arv[2*j+1], er2));
            }
#pragma unroll
            for (int o = 1; o <= 2; o <<= 1) {
                el1 += __shfl_xor_sync(0xffffffffu, el1, o);
                er1 += __shfl_xor_sync(0xffffffffu, er1, o);
                el2 += __shfl_xor_sync(0xffffffffu, el2, o);
                er2 += __shfl_xor_sync(0xffffffffu, er2, o);
            }
            if (tig == 0) {
                int r1 = bm + wm * 32 + i * 16 + grp;
                g_el[r1 * HH + hglob]       = el1;
                g_er[r1 * HH + hglob]       = er1;
                g_el[(r1 + 8) * HH + hglob] = el2;
                g_er[(r1 + 8) * HH + hglob] = er2;
            }
        }
    }
}

// ---------------- per-node edge-softmax aggregation (warp per node) ----------------
// Also emits bf16 hi/lo split of the activated output (next layer's GEMM input).
__global__ __launch_bounds__(256) void agg_kernel(const float* __restrict__ z,
                                                  const float* __restrict__ hprev,
                                                  float* __restrict__ hout,
                                                  int residual, int emit_bf16) {
    int n    = (blockIdx.x * blockDim.x + threadIdx.x) >> 5;
    int lane = threadIdx.x & 31;
    if (n >= NN) return;

    int base = g_rowptr[n];
    int deg  = g_rowptr[n + 1] - base;
    float4 er4 = ((const float4*)g_er)[n];

    float m0 = -1e30f, m1 = -1e30f, m2 = -1e30f, m3 = -1e30f;
    for (int k = lane; k < deg; k += 32) {
        int s = g_esrc[base + k];
        float4 e4 = ((const float4*)g_el)[s];
        m0 = fmaxf(m0, lrelu(e4.x + er4.x));
        m1 = fmaxf(m1, lrelu(e4.y + er4.y));
        m2 = fmaxf(m2, lrelu(e4.z + er4.z));
        m3 = fmaxf(m3, lrelu(e4.w + er4.w));
    }
#pragma unroll
    for (int o = 16; o >= 1; o >>= 1) {
        m0 = fmaxf(m0, __shfl_xor_sync(0xffffffffu, m0, o));
        m1 = fmaxf(m1, __shfl_xor_sync(0xffffffffu, m1, o));
        m2 = fmaxf(m2, __shfl_xor_sync(0xffffffffu, m2, o));
        m3 = fmaxf(m3, __shfl_xor_sync(0xffffffffu, m3, o));
    }

    int hh = lane >> 3;

    float acc0 = 0.f, acc1 = 0.f, acc2 = 0.f, acc3 = 0.f;
    float acc4 = 0.f, acc5 = 0.f, acc6 = 0.f, acc7 = 0.f;
    float ssum = 0.f;

    for (int c = 0; c < deg; c += 32) {
        int rem = deg - c; if (rem > 32) rem = 32;
        int    s_l = 0;
        float4 w4  = {0.f, 0.f, 0.f, 0.f};
        if (lane < rem) {
            s_l = g_esrc[base + c + lane];
            float4 e4 = ((const float4*)g_el)[s_l];
            w4.x = __expf(lrelu(e4.x + er4.x) - m0);
            w4.y = __expf(lrelu(e4.y + er4.y) - m1);
            w4.z = __expf(lrelu(e4.z + er4.z) - m2);
            w4.w = __expf(lrelu(e4.w + er4.w) - m3);
        }
        for (int k = 0; k < rem; k++) {
            int   s  = __shfl_sync(0xffffffffu, s_l, k);
            float wx = __shfl_sync(0xffffffffu, w4.x, k);
            float wy = __shfl_sync(0xffffffffu, w4.y, k);
            float wz = __shfl_sync(0xffffffffu, w4.z, k);
            float ww = __shfl_sync(0xffffffffu, w4.w, k);
            float w  = (hh == 0) ? wx : (hh == 1) ? wy : (hh == 2) ? wz : ww;
            ssum += w;
            const float4* zr = (const float4*)(z + (size_t)s * HD + lane * 8);
            float4 a = zr[0], b = zr[1];
            acc0 = fmaf(w, a.x, acc0); acc1 = fmaf(w, a.y, acc1);
            acc2 = fmaf(w, a.z, acc2); acc3 = fmaf(w, a.w, acc3);
            acc4 = fmaf(w, b.x, acc4); acc5 = fmaf(w, b.y, acc5);
            acc6 = fmaf(w, b.z, acc6); acc7 = fmaf(w, b.w, acc7);
        }
    }

    float inv = 1.f / ssum;
    float o8[8] = {acc0*inv, acc1*inv, acc2*inv, acc3*inv,
                   acc4*inv, acc5*inv, acc6*inv, acc7*inv};
    size_t ob = (size_t)n * HD + lane * 8;
    if (residual) {
        const float4* pp = (const float4*)(hprev + ob);
        float4 p0 = pp[0], p1 = pp[1];
        float pr[8] = {p0.x, p0.y, p0.z, p0.w, p1.x, p1.y, p1.z, p1.w};
#pragma unroll
        for (int i = 0; i < 8; i++) o8[i] = elu1(o8[i] + pr[i]);
    }
#pragma unroll
    for (int i = 0; i < 8; i++) o8[i] = elu1(o8[i]);
    float4 v0 = {o8[0], o8[1], o8[2], o8[3]};
    float4 v1 = {o8[4], o8[5], o8[6], o8[7]};
    *(float4*)(hout + ob)     = v0;
    *(float4*)(hout + ob + 4) = v1;

    if (emit_bf16) {   // hi/lo split for next layer's GEMM (replaces convA)
        __nv_bfloat16 hhi[8], hlo[8];
#pragma unroll
        for (int i = 0; i < 8; i++) {
            hhi[i] = __float2bfloat16(o8[i]);
            hlo[i] = __float2bfloat16(o8[i] - __bfloat162float(hhi[i]));
        }
        *(uint4*)(g_ahi + ob) = *(uint4*)hhi;
        *(uint4*)(g_alo + ob) = *(uint4*)hlo;
    }
}

// ---------------- pooling + classifier ----------------
__global__ __launch_bounds__(256) void pool_kernel(const float* __restrict__ h,
                                                   const float* __restrict__ Wc,
                                                   const float* __restrict__ bc,
                                                   float* __restrict__ out) {
    __shared__ float hg[HD];
    int g = blockIdx.x;
    int t = threadIdx.x;
    float s = 0.f;
    const float* base = h + (size_t)g * NPG * HD + t;
    for (int i = 0; i < NPG; i++) s += base[(size_t)i * HD];
    hg[t] = elu1(s * (1.f / NPG));
    __syncthreads();
    if (t < CC) {
        float acc = bc[t];
        for (int f = 0; f < HD; f++) acc = fmaf(hg[f], Wc[f * CC + t], acc);
        out[g * CC + t] = acc;
    }
}

// ---------------- launch ----------------
extern "C" void kernel_launch(void* const* d_in, const int* in_sizes, int n_in,
                              void* d_out, int out_size) {
    const float* x   = (const float*)d_in[0];
    const int*   src = (const int*)  d_in[1];
    const int*   dst = (const int*)  d_in[2];
    const float* W0  = (const float*)d_in[4];
    const float* al0 = (const float*)d_in[5];
    const float* ar0 = (const float*)d_in[6];
    const float* W1  = (const float*)d_in[7];
    const float* al1 = (const float*)d_in[8];
    const float* ar1 = (const float*)d_in[9];
    const float* W2  = (const float*)d_in[10];
    const float* al2 = (const float*)d_in[11];
    const float* ar2 = (const float*)d_in[12];
    const float* Wc  = (const float*)d_in[13];
    const float* bc  = (const float*)d_in[14];
    float* out = (float*)d_out;

    float *z, *hA, *hB;
    __nv_bfloat16 *ahi, *alo, *bhi, *blo;
    cudaGetSymbolAddress((void**)&z,   g_z);
    cudaGetSymbolAddress((void**)&hA,  g_hA);
    cudaGetSymbolAddress((void**)&hB,  g_hB);
    cudaGetSymbolAddress((void**)&ahi, g_ahi);
    cudaGetSymbolAddress((void**)&alo, g_alo);
    cudaGetSymbolAddress((void**)&bhi, g_bhi);
    cudaGetSymbolAddress((void**)&blo, g_blo);

    cudaFuncSetAttribute(gemm_mma_kernel,
                         cudaFuncAttributeMaxDynamicSharedMemorySize, SMEM_GEMM);

    // CSR by dst
    zero_deg_kernel<<<(NN + 255) / 256, 256>>>();
    hist_kernel<<<(EE + 255) / 256, 256>>>(dst);
    scan_kernel<<<1, 512>>>();
    scatter_kernel<<<(EE + 255) / 256, 256>>>(src, dst);

    // weight conversions
    convB_kernel<<<(128 * HD + 255) / 256, 256>>>(W0, 128 * HD, 0);
    convB_kernel<<<(256 * HD + 255) / 256, 256>>>(W1, 256 * HD, 1);
    convB_kernel<<<(256 * HD + 255) / 256, 256>>>(W2, 256 * HD, 2);

    dim3 ggrid(NN / 128, 2);

    // layer 0 (K=128, no residual)
    convA_kernel<<<(NN * 128 / 4 + 255) / 256, 256>>>(x, NN * 128 / 4);
    gemm_mma_kernel<<<ggrid, 256, SMEM_GEMM>>>(ahi, alo, bhi, blo, z, al0, ar0, 128);
    agg_kernel<<<NN / 8, 256>>>(z, nullptr, hA, 0, 1);

    // layer 1 (K=256, residual)
    gemm_mma_kernel<<<ggrid, 256, SMEM_GEMM>>>(ahi, alo, bhi + HD * HD,
                                               blo + HD * HD, z, al1, ar1, 256);
    agg_kernel<<<NN / 8, 256>>>(z, hA, hB, 1, 1);

    // layer 2 (K=256, residual)
    gemm_mma_kernel<<<ggrid, 256, SMEM_GEMM>>>(ahi, alo, bhi + 2 * HD * HD,
                                               blo + 2 * HD * HD, z, al2, ar2, 256);
    agg_kernel<<<NN / 8, 256>>>(z, hB, hA, 1, 0);

    pool_kernel<<<GG, 256>>>(hA, Wc, bc, out);
}

// round 6
// speedup vs baseline: 1.6271x; 1.0495x over previous
#include <cuda_runtime.h>
#include <cuda_bf16.h>
#include <math.h>
#include <stdint.h>

#define NN 20480
#define EE 327680
#define GG 64
#define HD 256     // H*D
#define HH 4
#define DD 64
#define CC 10
#define NPG (NN/GG)

// ---------------- scratch (static device globals; no allocation) ----------------
__device__ float g_z [NN*HD];
__device__ float g_hA[NN*HD];
__device__ float g_hB[NN*HD];
__device__ float g_el[NN*HH];
__device__ float g_er[NN*HH];
__device__ float g_elmax[4];
__device__ int   g_deg[NN];
__device__ int   g_rowptr[NN+1];
__device__ int   g_cursor[NN];
__device__ int   g_esrc[EE];
__device__ __nv_bfloat16 g_ahi[NN*HD];      // A split (per-layer reuse)
__device__ __nv_bfloat16 g_alo[NN*HD];
__device__ __nv_bfloat16 g_bhi[3][HD*HD];   // B split per layer: [K][256]
__device__ __nv_bfloat16 g_blo[3][HD*HD];

__device__ __forceinline__ float lrelu(float x) { return x > 0.f ? x : 0.2f * x; }
__device__ __forceinline__ float elu1 (float x) { return x > 0.f ? x : expm1f(x); }

__device__ __forceinline__ uint32_t smem_u32(const void* p) {
    uint32_t a;
    asm("{ .reg .u64 t; cvta.to.shared.u64 t, %1; cvt.u32.u64 %0, t; }" : "=r"(a) : "l"(p));
    return a;
}
__device__ __forceinline__ void ldmat4(uint32_t* r, uint32_t a) {
    asm volatile("ldmatrix.sync.aligned.m8n8.x4.shared.b16 {%0,%1,%2,%3}, [%4];"
        : "=r"(r[0]), "=r"(r[1]), "=r"(r[2]), "=r"(r[3]) : "r"(a));
}
__device__ __forceinline__ void ldmat4t(uint32_t* r, uint32_t a) {
    asm volatile("ldmatrix.sync.aligned.m8n8.x4.trans.shared.b16 {%0,%1,%2,%3}, [%4];"
        : "=r"(r[0]), "=r"(r[1]), "=r"(r[2]), "=r"(r[3]) : "r"(a));
}
__device__ __forceinline__ void mma16816(float* c, const uint32_t* a, const uint32_t* b) {
    asm volatile(
        "mma.sync.aligned.m16n8k16.row.col.f32.bf16.bf16.f32 "
        "{%0,%1,%2,%3}, {%4,%5,%6,%7}, {%8,%9}, {%0,%1,%2,%3};"
        : "+f"(c[0]), "+f"(c[1]), "+f"(c[2]), "+f"(c[3])
        : "r"(a[0]), "r"(a[1]), "r"(a[2]), "r"(a[3]), "r"(b[0]), "r"(b[1]));
}
#define CP16(s, g) asm volatile("cp.async.cg.shared.global [%0], [%1], 16;" \
    :: "r"(s), "l"(__cvta_generic_to_global(g)))
#define CP_COMMIT() asm volatile("cp.async.commit_group;" ::: "memory")
#define CP_WAIT0()  asm volatile("cp.async.wait_group 0;" ::: "memory")
#define CP_WAIT1()  asm volatile("cp.async.wait_group 1;" ::: "memory")

// ---------------- CSR build ----------------
__global__ void zero_deg_kernel() {
    int i = blockIdx.x * blockDim.x + threadIdx.x;
    if (i < NN) g_deg[i] = 0;
}
__global__ void hist_kernel(const int* __restrict__ dst) {
    int i = blockIdx.x * blockDim.x + threadIdx.x;
    if (i < EE) atomicAdd(&g_deg[dst[i]], 1);
}
__global__ void scan_kernel() {
    __shared__ int part[512];
    const int CH = NN / 512;
    int t = threadIdx.x;
    int s = 0;
    for (int i = 0; i < CH; i++) s += g_deg[t*CH + i];
    part[t] = s;
    __syncthreads();
    if (t == 0) {
        int r = 0;
        for (int i = 0; i < 512; i++) { int v = part[i]; part[i] = r; r += v; }
        g_rowptr[NN] = r;
    }
    __syncthreads();
    int run = part[t];
    for (int i = 0; i < CH; i++) {
        int idx = t*CH + i;
        g_rowptr[idx] = run;
        g_cursor[idx] = run;
        run += g_deg[idx];
    }
}
__global__ void scatter_kernel(const int* __restrict__ src, const int* __restrict__ dst) {
    int i = blockIdx.x * blockDim.x + threadIdx.x;
    if (i < EE) {
        int p = atomicAdd(&g_cursor[dst[i]], 1);
        g_esrc[p] = src[i];
    }
}

// ---------------- fp32 -> bf16 hi/lo split (layer-0 input only) ----------------
__global__ void convA_kernel(const float* __restrict__ A, int n4) {
    int i = blockIdx.x * blockDim.x + threadIdx.x;
    if (i >= n4) return;
    float4 v = ((const float4*)A)[i];
    __nv_bfloat16 hx = __float2bfloat16(v.x), hy = __float2bfloat16(v.y);
    __nv_bfloat16 hz = __float2bfloat16(v.z), hw = __float2bfloat16(v.w);
    __nv_bfloat16 lx = __float2bfloat16(v.x - __bfloat162float(hx));
    __nv_bfloat16 ly = __float2bfloat16(v.y - __bfloat162float(hy));
    __nv_bfloat16 lz = __float2bfloat16(v.z - __bfloat162float(hz));
    __nv_bfloat16 lw = __float2bfloat16(v.w - __bfloat162float(hw));
    ((__nv_bfloat162*)g_ahi)[2*i]   = __nv_bfloat162(hx, hy);
    ((__nv_bfloat162*)g_ahi)[2*i+1] = __nv_bfloat162(hz, hw);
    ((__nv_bfloat162*)g_alo)[2*i]   = __nv_bfloat162(lx, ly);
    ((__nv_bfloat162*)g_alo)[2*i+1] = __nv_bfloat162(lz, lw);
}
// all three weight matrices in one launch
__global__ void convB_kernel(const float* __restrict__ W0,
                             const float* __restrict__ W1,
                             const float* __restrict__ W2) {
    int i = blockIdx.x * blockDim.x + threadIdx.x;   // 0 .. 163839
    const float* B; int layer, off;
    if (i < 128 * HD)           { B = W0; layer = 0; off = i; }
    else if (i < (128+256)*HD)  { B = W1; layer = 1; off = i - 128 * HD; }
    else if (i < (128+512)*HD)  { B = W2; layer = 2; off = i - (128+256) * HD; }
    else return;
    float v = B[off];
    __nv_bfloat16 h = __float2bfloat16(v);
    g_bhi[layer][off] = h;
    g_blo[layer][off] = __float2bfloat16(v - __bfloat162float(h));
}

// ---------------- per-head global max of el (softmax shift) ----------------
__global__ void elmax_kernel() {
    __shared__ float4 red[32];
    int t = threadIdx.x, lane = t & 31, w = t >> 5;   // 1024 threads
    float m0 = -1e30f, m1 = -1e30f, m2 = -1e30f, m3 = -1e30f;
    for (int i = t; i < NN; i += 1024) {
        float4 e = ((const float4*)g_el)[i];
        m0 = fmaxf(m0, e.x); m1 = fmaxf(m1, e.y);
        m2 = fmaxf(m2, e.z); m3 = fmaxf(m3, e.w);
    }
#pragma unroll
    for (int o = 16; o >= 1; o >>= 1) {
        m0 = fmaxf(m0, __shfl_xor_sync(0xffffffffu, m0, o));
        m1 = fmaxf(m1, __shfl_xor_sync(0xffffffffu, m1, o));
        m2 = fmaxf(m2, __shfl_xor_sync(0xffffffffu, m2, o));
        m3 = fmaxf(m3, __shfl_xor_sync(0xffffffffu, m3, o));
    }
    if (lane == 0) red[w] = make_float4(m0, m1, m2, m3);
    __syncthreads();
    if (w == 0) {
        float4 v = red[lane];
        m0 = v.x; m1 = v.y; m2 = v.z; m3 = v.w;
#pragma unroll
        for (int o = 16; o >= 1; o >>= 1) {
            m0 = fmaxf(m0, __shfl_xor_sync(0xffffffffu, m0, o));
            m1 = fmaxf(m1, __shfl_xor_sync(0xffffffffu, m1, o));
            m2 = fmaxf(m2, __shfl_xor_sync(0xffffffffu, m2, o));
            m3 = fmaxf(m3, __shfl_xor_sync(0xffffffffu, m3, o));
        }
        if (lane == 0) *(float4*)g_elmax = make_float4(m0, m1, m2, m3);
    }
}

// ---------------- mma.sync GEMM + fused attn projections ----------------
#define ARB 80        // A smem row bytes (32 bf16 + pad)
#define BRB 272       // B smem row bytes (128 bf16 + pad)
#define S_ALO 10240
#define S_BHI 20480
#define S_BLO 29184
#define BUF   37888
#define SMEM_GEMM (2*BUF)

__global__ __launch_bounds__(256, 2) void gemm_mma_kernel(
    const __nv_bfloat16* __restrict__ Ahi, const __nv_bfloat16* __restrict__ Alo,
    const __nv_bfloat16* __restrict__ Bhi, const __nv_bfloat16* __restrict__ Blo,
    float* __restrict__ C,
    const float* __restrict__ al, const float* __restrict__ ar, int K) {
    extern __shared__ char sm[];
    uint32_t sb = smem_u32(sm);
    int tid = threadIdx.x, lane = tid & 31, wid = tid >> 5;
    int wm = wid & 3, wn = wid >> 2;
    int bm = blockIdx.x * 128, bn = blockIdx.y * 128;

    float acc[2][8][4];
#pragma unroll
    for (int i = 0; i < 2; i++)
#pragma unroll
        for (int j = 0; j < 8; j++)
#pragma unroll
            for (int q = 0; q < 4; q++) acc[i][j][q] = 0.f;

    auto issue = [&](int c, int buf) {
        int k0 = c * 32;
        uint32_t s0 = sb + buf * BUF;
#pragma unroll
        for (int r = 0; r < 2; r++) {
            int idx  = tid + r * 256;
            int arow = idx >> 2, ach = idx & 3;
            const __nv_bfloat16* gh = Ahi + (size_t)(bm + arow) * K + k0 + ach * 8;
            const __nv_bfloat16* gl = Alo + (size_t)(bm + arow) * K + k0 + ach * 8;
            CP16(s0 + arow * ARB + ach * 16, gh);
            CP16(s0 + S_ALO + arow * ARB + ach * 16, gl);
            int brow = idx >> 4, bch = idx & 15;
            const __nv_bfloat16* bh = Bhi + (size_t)(k0 + brow) * HD + bn + bch * 8;
            const __nv_bfloat16* bl = Blo + (size_t)(k0 + brow) * HD + bn + bch * 8;
            CP16(s0 + S_BHI + brow * BRB + bch * 16, bh);
            CP16(s0 + S_BLO + brow * BRB + bch * 16, bl);
        }
    };

    auto compute = [&](int buf) {
        uint32_t s0 = sb + buf * BUF;
#pragma unroll
        for (int ks = 0; ks < 32; ks += 16) {
            uint32_t ah[2][4], alr[2][4];
#pragma unroll
            for (int i = 0; i < 2; i++) {
                int row = wm * 32 + i * 16 + (lane & 15);
                uint32_t ad = s0 + row * ARB + (ks + (lane >> 4) * 8) * 2;
                ldmat4(ah[i], ad);
                ldmat4(alr[i], ad + S_ALO);
            }
#pragma unroll
            for (int jj = 0; jj < 4; jj++) {
                int krow = ks + (lane & 15);
                int ncol = wn * 64 + jj * 16 + (lane >> 4) * 8;
                uint32_t bd = s0 + S_BHI + krow * BRB + ncol * 2;
                uint32_t bh[4], bl[4];
                ldmat4t(bh, bd);
                ldmat4t(bl, bd + (S_BLO - S_BHI));
#pragma unroll
                for (int i = 0; i < 2; i++) {
                    mma16816(acc[i][2*jj],   ah[i],  bh);
                    mma16816(acc[i][2*jj],   alr[i], bh);
                    mma16816(acc[i][2*jj],   ah[i],  bl);
                    mma16816(acc[i][2*jj+1], ah[i],  bh + 2);
                    mma16816(acc[i][2*jj+1], alr[i], bh + 2);
                    mma16816(acc[i][2*jj+1], ah[i],  bl + 2);
                }
            }
        }
    };

    int nch = K >> 5;
    issue(0, 0);
    CP_COMMIT();
    for (int c = 0; c < nch; c++) {
        if (c + 1 < nch) {
            issue(c + 1, (c + 1) & 1);
            CP_COMMIT();
            CP_WAIT1();
        } else {
            CP_WAIT0();
        }
        __syncthreads();
        compute(c & 1);
        __syncthreads();
    }

    int grp = lane >> 2, tig = lane & 3;

#pragma unroll
    for (int i = 0; i < 2; i++) {
        int rbase = bm + wm * 32 + i * 16 + grp;
#pragma unroll
        for (int j = 0; j < 8; j++) {
            int col = bn + wn * 64 + j * 8 + tig * 2;
            float2 v0 = {acc[i][j][0], acc[i][j][1]};
            float2 v1 = {acc[i][j][2], acc[i][j][3]};
            *(float2*)(C + (size_t)rbase * HD + col)       = v0;
            *(float2*)(C + (size_t)(rbase + 8) * HD + col) = v1;
        }
    }

    {   // fused el/er for head hglob
        int hglob = (bn >> 6) + wn;
        const float* alh = al + hglob * DD;
        const float* arh = ar + hglob * DD;
        float alv[16], arv[16];
#pragma unroll
        for (int j = 0; j < 8; j++) {
            int cw = j * 8 + tig * 2;
            alv[2*j]   = alh[cw];   alv[2*j+1] = alh[cw+1];
            arv[2*j]   = arh[cw];   arv[2*j+1] = arh[cw+1];
        }
#pragma unroll
        for (int i = 0; i < 2; i++) {
            float el1 = 0.f, er1 = 0.f, el2 = 0.f, er2 = 0.f;
#pragma unroll
            for (int j = 0; j < 8; j++) {
                el1 = fmaf(acc[i][j][0], alv[2*j], fmaf(acc[i][j][1], alv[2*j+1], el1));
                er1 = fmaf(acc[i][j][0], arv[2*j], fmaf(acc[i][j][1], arv[2*j+1], er1));
                el2 = fmaf(acc[i][j][2], alv[2*j], fmaf(acc[i][j][3], alv[2*j+1], el2));
                er2 = fmaf(acc[i][j][2], arv[2*j], fmaf(acc[i][j][3], arv[2*j+1], er2));
            }
#pragma unroll
            for (int o = 1; o <= 2; o <<= 1) {
                el1 += __shfl_xor_sync(0xffffffffu, el1, o);
                er1 += __shfl_xor_sync(0xffffffffu, er1, o);
                el2 += __shfl_xor_sync(0xffffffffu, el2, o);
                er2 += __shfl_xor_sync(0xffffffffu, er2, o);
            }
            if (tig == 0) {
                int r1 = bm + wm * 32 + i * 16 + grp;
                g_el[r1 * HH + hglob]       = el1;
                g_er[r1 * HH + hglob]       = er1;
                g_el[(r1 + 8) * HH + hglob] = el2;
                g_er[(r1 + 8) * HH + hglob] = er2;
            }
        }
    }
}

// ---------------- per-node edge-softmax aggregation (warp per node) ----------------
// Single pass: uses per-head GLOBAL el-max for the softmax shift (shift-invariant).
__global__ __launch_bounds__(256) void agg_kernel(const float* __restrict__ z,
                                                  const float* __restrict__ hprev,
                                                  float* __restrict__ hout,
                                                  int residual, int emit_bf16) {
    int n    = (blockIdx.x * blockDim.x + threadIdx.x) >> 5;
    int lane = threadIdx.x & 31;
    if (n >= NN) return;

    int base = g_rowptr[n];
    int deg  = g_rowptr[n + 1] - base;
    float4 er4 = ((const float4*)g_er)[n];
    float4 M   = *(const float4*)g_elmax;
    float m0 = lrelu(M.x + er4.x), m1 = lrelu(M.y + er4.y);
    float m2 = lrelu(M.z + er4.z), m3 = lrelu(M.w + er4.w);

    int hh = lane >> 3;

    float acc0 = 0.f, acc1 = 0.f, acc2 = 0.f, acc3 = 0.f;
    float acc4 = 0.f, acc5 = 0.f, acc6 = 0.f, acc7 = 0.f;
    float ssum = 0.f;

    for (int c = 0; c < deg; c += 32) {
        int rem = deg - c; if (rem > 32) rem = 32;
        int    s_l = 0;
        float4 w4  = {0.f, 0.f, 0.f, 0.f};
        if (lane < rem) {
            s_l = g_esrc[base + c + lane];
            float4 e4 = ((const float4*)g_el)[s_l];
            w4.x = __expf(lrelu(e4.x + er4.x) - m0);
            w4.y = __expf(lrelu(e4.y + er4.y) - m1);
            w4.z = __expf(lrelu(e4.z + er4.z) - m2);
            w4.w = __expf(lrelu(e4.w + er4.w) - m3);
        }
#pragma unroll 4
        for (int k = 0; k < rem; k++) {
            int   s  = __shfl_sync(0xffffffffu, s_l, k);
            float wx = __shfl_sync(0xffffffffu, w4.x, k);
            float wy = __shfl_sync(0xffffffffu, w4.y, k);
            float wz = __shfl_sync(0xffffffffu, w4.z, k);
            float ww = __shfl_sync(0xffffffffu, w4.w, k);
            float w  = (hh == 0) ? wx : (hh == 1) ? wy : (hh == 2) ? wz : ww;
            ssum += w;
            const float4* zr = (const float4*)(z + (size_t)s * HD + lane * 8);
            float4 a = zr[0], b = zr[1];
            acc0 = fmaf(w, a.x, acc0); acc1 = fmaf(w, a.y, acc1);
            acc2 = fmaf(w, a.z, acc2); acc3 = fmaf(w, a.w, acc3);
            acc4 = fmaf(w, b.x, acc4); acc5 = fmaf(w, b.y, acc5);
            acc6 = fmaf(w, b.z, acc6); acc7 = fmaf(w, b.w, acc7);
        }
    }

    float inv = 1.f / ssum;
    float o8[8] = {acc0*inv, acc1*inv, acc2*inv, acc3*inv,
                   acc4*inv, acc5*inv, acc6*inv, acc7*inv};
    size_t ob = (size_t)n * HD + lane * 8;
    if (residual) {
        const float4* pp = (const float4*)(hprev + ob);
        float4 p0 = pp[0], p1 = pp[1];
        float pr[8] = {p0.x, p0.y, p0.z, p0.w, p1.x, p1.y, p1.z, p1.w};
#pragma unroll
        for (int i = 0; i < 8; i++) o8[i] = elu1(o8[i] + pr[i]);
    }
#pragma unroll
    for (int i = 0; i < 8; i++) o8[i] = elu1(o8[i]);
    float4 v0 = {o8[0], o8[1], o8[2], o8[3]};
    float4 v1 = {o8[4], o8[5], o8[6], o8[7]};
    *(float4*)(hout + ob)     = v0;
    *(float4*)(hout + ob + 4) = v1;

    if (emit_bf16) {
        __nv_bfloat16 hhi[8], hlo[8];
#pragma unroll
        for (int i = 0; i < 8; i++) {
            hhi[i] = __float2bfloat16(o8[i]);
            hlo[i] = __float2bfloat16(o8[i] - __bfloat162float(hhi[i]));
        }
        *(uint4*)(g_ahi + ob) = *(uint4*)hhi;
        *(uint4*)(g_alo + ob) = *(uint4*)hlo;
    }
}

// ---------------- pooling + classifier ----------------
__global__ __launch_bounds__(256) void pool_kernel(const float* __restrict__ h,
                                                   const float* __restrict__ Wc,
                                                   const float* __restrict__ bc,
                                                   float* __restrict__ out) {
    __shared__ float hg[HD];
    int g = blockIdx.x;
    int t = threadIdx.x;
    float s = 0.f;
    const float* base = h + (size_t)g * NPG * HD + t;
    for (int i = 0; i < NPG; i++) s += base[(size_t)i * HD];
    hg[t] = elu1(s * (1.f / NPG));
    __syncthreads();
    if (t < CC) {
        float acc = bc[t];
        for (int f = 0; f < HD; f++) acc = fmaf(hg[f], Wc[f * CC + t], acc);
        out[g * CC + t] = acc;
    }
}

// ---------------- launch ----------------
extern "C" void kernel_launch(void* const* d_in, const int* in_sizes, int n_in,
                              void* d_out, int out_size) {
    const float* x   = (const float*)d_in[0];
    const int*   src = (const int*)  d_in[1];
    const int*   dst = (const int*)  d_in[2];
    const float* W0  = (const float*)d_in[4];
    const float* al0 = (const float*)d_in[5];
    const float* ar0 = (const float*)d_in[6];
    const float* W1  = (const float*)d_in[7];
    const float* al1 = (const float*)d_in[8];
    const float* ar1 = (const float*)d_in[9];
    const float* W2  = (const float*)d_in[10];
    const float* al2 = (const float*)d_in[11];
    const float* ar2 = (const float*)d_in[12];
    const float* Wc  = (const float*)d_in[13];
    const float* bc  = (const float*)d_in[14];
    float* out = (float*)d_out;

    float *z, *hA, *hB;
    __nv_bfloat16 *ahi, *alo, *bhi, *blo;
    cudaGetSymbolAddress((void**)&z,   g_z);
    cudaGetSymbolAddress((void**)&hA,  g_hA);
    cudaGetSymbolAddress((void**)&hB,  g_hB);
    cudaGetSymbolAddress((void**)&ahi, g_ahi);
    cudaGetSymbolAddress((void**)&alo, g_alo);
    cudaGetSymbolAddress((void**)&bhi, g_bhi);
    cudaGetSymbolAddress((void**)&blo, g_blo);

    cudaFuncSetAttribute(gemm_mma_kernel,
                         cudaFuncAttributeMaxDynamicSharedMemorySize, SMEM_GEMM);

    // fork CSR build onto a side stream, overlapped with conv + layer-0 GEMM.
    // (host code runs only on the correctness call and the capture call;
    //  graph replays execute device work only, so per-call handles are fine)
    cudaStream_t s2;
    cudaStreamCreateWithFlags(&s2, cudaStreamNonBlocking);
    cudaEvent_t evFork, evJoin;
    cudaEventCreateWithFlags(&evFork, cudaEventDisableTiming);
    cudaEventCreateWithFlags(&evJoin, cudaEventDisableTiming);

    cudaEventRecord(evFork, 0);
    cudaStreamWaitEvent(s2, evFork, 0);
    zero_deg_kernel<<<(NN + 255) / 256, 256, 0, s2>>>();
    hist_kernel<<<(EE + 255) / 256, 256, 0, s2>>>(dst);
    scan_kernel<<<1, 512, 0, s2>>>();
    scatter_kernel<<<(EE + 255) / 256, 256, 0, s2>>>(src, dst);
    cudaEventRecord(evJoin, s2);

    // main stream: conversions + layer-0 GEMM (independent of CSR)
    convB_kernel<<<((128 + 512) * HD + 255) / 256, 256>>>(W0, W1, W2);
    convA_kernel<<<(NN * 128 / 4 + 255) / 256, 256>>>(x, NN * 128 / 4);

    dim3 ggrid(NN / 128, 2);
    gemm_mma_kernel<<<ggrid, 256, SMEM_GEMM>>>(ahi, alo, bhi, blo, z, al0, ar0, 128);
    elmax_kernel<<<1, 1024>>>();

    cudaStreamWaitEvent(0, evJoin, 0);   // CSR ready before first agg
    agg_kernel<<<NN / 8, 256>>>(z, nullptr, hA, 0, 1);

    // layer 1
    gemm_mma_kernel<<<ggrid, 256, SMEM_GEMM>>>(ahi, alo, bhi + HD * HD,
                                               blo + HD * HD, z, al1, ar1, 256);
    elmax_kernel<<<1, 1024>>>();
    agg_kernel<<<NN / 8, 256>>>(z, hA, hB, 1, 1);

    // layer 2
    gemm_mma_kernel<<<ggrid, 256, SMEM_GEMM>>>(ahi, alo, bhi + 2 * HD * HD,
                                               blo + 2 * HD * HD, z, al2, ar2, 256);
    elmax_kernel<<<1, 1024>>>();
    agg_kernel<<<NN / 8, 256>>>(z, hB, hA, 1, 0);

    pool_kernel<<<GG, 256>>>(hA, Wc, bc, out);
}

// round 7
// speedup vs baseline: 1.7494x; 1.0752x over previous
#include <cuda_runtime.h>
#include <cuda_bf16.h>
#include <math.h>
#include <stdint.h>

#define NN 20480
#define EE 327680
#define GG 64
#define HD 256     // H*D
#define HH 4
#define DD 64
#define CC 10
#define NPG (NN/GG)

// ---------------- scratch (static device globals; no allocation) ----------------
__device__ __nv_bfloat16 g_zb[NN*HD];        // z in bf16 (agg gather operand)
__device__ float g_hA[NN*HD];
__device__ float g_hB[NN*HD];
__device__ float g_el[NN*HH];
__device__ float g_er[NN*HH];
__device__ unsigned g_elmaxU[3*HH];          // encoded per-head el max, per layer
__device__ int   g_deg[NN];
__device__ int   g_rowptr[NN+1];
__device__ int   g_cursor[NN];
__device__ int   g_esrc[EE];
__device__ __nv_bfloat16 g_ahi[NN*HD];       // GEMM A hi/lo split
__device__ __nv_bfloat16 g_alo[NN*HD];
__device__ __nv_bfloat16 g_bhi[3][HD*HD];    // B split per layer: [K][256]
__device__ __nv_bfloat16 g_blo[3][HD*HD];

__device__ __forceinline__ float lrelu(float x) { return x > 0.f ? x : 0.2f * x; }
__device__ __forceinline__ float elu1 (float x) { return x > 0.f ? x : expm1f(x); }

// monotone float<->uint encoding for atomicMax on floats
__device__ __forceinline__ unsigned fenc(float f) {
    unsigned u = __float_as_uint(f);
    return (u & 0x80000000u) ? ~u : (u | 0x80000000u);
}
__device__ __forceinline__ float fdec(unsigned u) {
    return (u & 0x80000000u) ? __uint_as_float(u & 0x7fffffffu) : __uint_as_float(~u);
}

__device__ __forceinline__ uint32_t smem_u32(const void* p) {
    uint32_t a;
    asm("{ .reg .u64 t; cvta.to.shared.u64 t, %1; cvt.u32.u64 %0, t; }" : "=r"(a) : "l"(p));
    return a;
}
__device__ __forceinline__ void ldmat4(uint32_t* r, uint32_t a) {
    asm volatile("ldmatrix.sync.aligned.m8n8.x4.shared.b16 {%0,%1,%2,%3}, [%4];"
        : "=r"(r[0]), "=r"(r[1]), "=r"(r[2]), "=r"(r[3]) : "r"(a));
}
__device__ __forceinline__ void ldmat4t(uint32_t* r, uint32_t a) {
    asm volatile("ldmatrix.sync.aligned.m8n8.x4.trans.shared.b16 {%0,%1,%2,%3}, [%4];"
        : "=r"(r[0]), "=r"(r[1]), "=r"(r[2]), "=r"(r[3]) : "r"(a));
}
__device__ __forceinline__ void mma16816(float* c, const uint32_t* a, const uint32_t* b) {
    asm volatile(
        "mma.sync.aligned.m16n8k16.row.col.f32.bf16.bf16.f32 "
        "{%0,%1,%2,%3}, {%4,%5,%6,%7}, {%8,%9}, {%0,%1,%2,%3};"
        : "+f"(c[0]), "+f"(c[1]), "+f"(c[2]), "+f"(c[3])
        : "r"(a[0]), "r"(a[1]), "r"(a[2]), "r"(a[3]), "r"(b[0]), "r"(b[1]));
}
#define CP16(s, g) asm volatile("cp.async.cg.shared.global [%0], [%1], 16;" \
    :: "r"(s), "l"(__cvta_generic_to_global(g)))
#define CP_COMMIT() asm volatile("cp.async.commit_group;" ::: "memory")
#define CP_WAIT0()  asm volatile("cp.async.wait_group 0;" ::: "memory")
#define CP_WAIT1()  asm volatile("cp.async.wait_group 1;" ::: "memory")

// ---------------- CSR build ----------------
__global__ void zero_deg_kernel() {
    int i = blockIdx.x * blockDim.x + threadIdx.x;
    if (i < NN) g_deg[i] = 0;
}
__global__ void hist_kernel(const int* __restrict__ dst) {
    int i = blockIdx.x * blockDim.x + threadIdx.x;
    if (i < EE) atomicAdd(&g_deg[dst[i]], 1);
}
__global__ void scan_kernel() {
    __shared__ int part[512];
    const int CH = NN / 512;
    int t = threadIdx.x;
    int s = 0;
    for (int i = 0; i < CH; i++) s += g_deg[t*CH + i];
    part[t] = s;
    __syncthreads();
    if (t == 0) {
        int r = 0;
        for (int i = 0; i < 512; i++) { int v = part[i]; part[i] = r; r += v; }
        g_rowptr[NN] = r;
    }
    __syncthreads();
    int run = part[t];
    for (int i = 0; i < CH; i++) {
        int idx = t*CH + i;
        g_rowptr[idx] = run;
        g_cursor[idx] = run;
        run += g_deg[idx];
    }
}
__global__ void scatter_kernel(const int* __restrict__ src, const int* __restrict__ dst) {
    int i = blockIdx.x * blockDim.x + threadIdx.x;
    if (i < EE) {
        int p = atomicAdd(&g_cursor[dst[i]], 1);
        g_esrc[p] = src[i];
    }
}

// ---------------- fp32 -> bf16 hi/lo split (layer-0 input only) ----------------
__global__ void convA_kernel(const float* __restrict__ A, int n4) {
    int i = blockIdx.x * blockDim.x + threadIdx.x;
    if (i >= n4) return;
    float4 v = ((const float4*)A)[i];
    __nv_bfloat16 hx = __float2bfloat16(v.x), hy = __float2bfloat16(v.y);
    __nv_bfloat16 hz = __float2bfloat16(v.z), hw = __float2bfloat16(v.w);
    __nv_bfloat16 lx = __float2bfloat16(v.x - __bfloat162float(hx));
    __nv_bfloat16 ly = __float2bfloat16(v.y - __bfloat162float(hy));
    __nv_bfloat16 lz = __float2bfloat16(v.z - __bfloat162float(hz));
    __nv_bfloat16 lw = __float2bfloat16(v.w - __bfloat162float(hw));
    ((__nv_bfloat162*)g_ahi)[2*i]   = __nv_bfloat162(hx, hy);
    ((__nv_bfloat162*)g_ahi)[2*i+1] = __nv_bfloat162(hz, hw);
    ((__nv_bfloat162*)g_alo)[2*i]   = __nv_bfloat162(lx, ly);
    ((__nv_bfloat162*)g_alo)[2*i+1] = __nv_bfloat162(lz, lw);
}
// all three weight matrices in one launch; also resets elmax buffers (per replay)
__global__ void convB_kernel(const float* __restrict__ W0,
                             const float* __restrict__ W1,
                             const float* __restrict__ W2) {
    int i = blockIdx.x * blockDim.x + threadIdx.x;
    if (blockIdx.x == 0 && threadIdx.x < 3 * HH) g_elmaxU[threadIdx.x] = 0u;
    const float* B; int layer, off;
    if (i < 128 * HD)           { B = W0; layer = 0; off = i; }
    else if (i < (128+256)*HD)  { B = W1; layer = 1; off = i - 128 * HD; }
    else if (i < (128+512)*HD)  { B = W2; layer = 2; off = i - (128+256) * HD; }
    else return;
    float v = B[off];
    __nv_bfloat16 h = __float2bfloat16(v);
    g_bhi[layer][off] = h;
    g_blo[layer][off] = __float2bfloat16(v - __bfloat162float(h));
}

// ---------------- mma.sync GEMM + fused attn projections + fused el-max ----------------
#define ARB 80        // A smem row bytes (32 bf16 + pad)
#define BRB 272       // B smem row bytes (128 bf16 + pad)
#define S_ALO 10240
#define S_BHI 20480
#define S_BLO 29184
#define BUF   37888
#define SMEM_GEMM (2*BUF)

__global__ __launch_bounds__(256, 2) void gemm_mma_kernel(
    const __nv_bfloat16* __restrict__ Ahi, const __nv_bfloat16* __restrict__ Alo,
    const __nv_bfloat16* __restrict__ Bhi, const __nv_bfloat16* __restrict__ Blo,
    __nv_bfloat16* __restrict__ Zb, unsigned* __restrict__ elmaxU,
    const float* __restrict__ al, const float* __restrict__ ar, int K) {
    extern __shared__ char sm[];
    uint32_t sb = smem_u32(sm);
    int tid = threadIdx.x, lane = tid & 31, wid = tid >> 5;
    int wm = wid & 3, wn = wid >> 2;
    int bm = blockIdx.x * 128, bn = blockIdx.y * 128;

    float acc[2][8][4];
#pragma unroll
    for (int i = 0; i < 2; i++)
#pragma unroll
        for (int j = 0; j < 8; j++)
#pragma unroll
            for (int q = 0; q < 4; q++) acc[i][j][q] = 0.f;

    auto issue = [&](int c, int buf) {
        int k0 = c * 32;
        uint32_t s0 = sb + buf * BUF;
#pragma unroll
        for (int r = 0; r < 2; r++) {
            int idx  = tid + r * 256;
            int arow = idx >> 2, ach = idx & 3;
            const __nv_bfloat16* gh = Ahi + (size_t)(bm + arow) * K + k0 + ach * 8;
            const __nv_bfloat16* gl = Alo + (size_t)(bm + arow) * K + k0 + ach * 8;
            CP16(s0 + arow * ARB + ach * 16, gh);
            CP16(s0 + S_ALO + arow * ARB + ach * 16, gl);
            int brow = idx >> 4, bch = idx & 15;
            const __nv_bfloat16* bh = Bhi + (size_t)(k0 + brow) * HD + bn + bch * 8;
            const __nv_bfloat16* bl = Blo + (size_t)(k0 + brow) * HD + bn + bch * 8;
            CP16(s0 + S_BHI + brow * BRB + bch * 16, bh);
            CP16(s0 + S_BLO + brow * BRB + bch * 16, bl);
        }
    };

    auto compute = [&](int buf) {
        uint32_t s0 = sb + buf * BUF;
#pragma unroll
        for (int ks = 0; ks < 32; ks += 16) {
            uint32_t ah[2][4], alr[2][4];
#pragma unroll
            for (int i = 0; i < 2; i++) {
                int row = wm * 32 + i * 16 + (lane & 15);
                uint32_t ad = s0 + row * ARB + (ks + (lane >> 4) * 8) * 2;
                ldmat4(ah[i], ad);
                ldmat4(alr[i], ad + S_ALO);
            }
#pragma unroll
            for (int jj = 0; jj < 4; jj++) {
                int krow = ks + (lane & 15);
                int ncol = wn * 64 + jj * 16 + (lane >> 4) * 8;
                uint32_t bd = s0 + S_BHI + krow * BRB + ncol * 2;
                uint32_t bh[4], bl[4];
                ldmat4t(bh, bd);
                ldmat4t(bl, bd + (S_BLO - S_BHI));
#pragma unroll
                for (int i = 0; i < 2; i++) {
                    mma16816(acc[i][2*jj],   ah[i],  bh);
                    mma16816(acc[i][2*jj],   alr[i], bh);
                    mma16816(acc[i][2*jj],   ah[i],  bl);
                    mma16816(acc[i][2*jj+1], ah[i],  bh + 2);
                    mma16816(acc[i][2*jj+1], alr[i], bh + 2);
                    mma16816(acc[i][2*jj+1], ah[i],  bl + 2);
                }
            }
        }
    };

    int nch = K >> 5;
    issue(0, 0);
    CP_COMMIT();
    for (int c = 0; c < nch; c++) {
        if (c + 1 < nch) {
            issue(c + 1, (c + 1) & 1);
            CP_COMMIT();
            CP_WAIT1();
        } else {
            CP_WAIT0();
        }
        __syncthreads();
        compute(c & 1);
        __syncthreads();
    }

    int grp = lane >> 2, tig = lane & 3;

    // ---- store z as bf16 ----
#pragma unroll
    for (int i = 0; i < 2; i++) {
        int rbase = bm + wm * 32 + i * 16 + grp;
#pragma unroll
        for (int j = 0; j < 8; j++) {
            int col = bn + wn * 64 + j * 8 + tig * 2;
            __nv_bfloat162 b0 = __floats2bfloat162_rn(acc[i][j][0], acc[i][j][1]);
            __nv_bfloat162 b1 = __floats2bfloat162_rn(acc[i][j][2], acc[i][j][3]);
            *(__nv_bfloat162*)(Zb + (size_t)rbase * HD + col)       = b0;
            *(__nv_bfloat162*)(Zb + (size_t)(rbase + 8) * HD + col) = b1;
        }
    }

    {   // ---- fused el/er for head hglob + global el-max atomic ----
        int hglob = (bn >> 6) + wn;
        const float* alh = al + hglob * DD;
        const float* arh = ar + hglob * DD;
        float alv[16], arv[16];
#pragma unroll
        for (int j = 0; j < 8; j++) {
            int cw = j * 8 + tig * 2;
            alv[2*j]   = alh[cw];   alv[2*j+1] = alh[cw+1];
            arv[2*j]   = arh[cw];   arv[2*j+1] = arh[cw+1];
        }
        float wmax = -1e30f;
#pragma unroll
        for (int i = 0; i < 2; i++) {
            float el1 = 0.f, er1 = 0.f, el2 = 0.f, er2 = 0.f;
#pragma unroll
            for (int j = 0; j < 8; j++) {
                el1 = fmaf(acc[i][j][0], alv[2*j], fmaf(acc[i][j][1], alv[2*j+1], el1));
                er1 = fmaf(acc[i][j][0], arv[2*j], fmaf(acc[i][j][1], arv[2*j+1], er1));
                el2 = fmaf(acc[i][j][2], alv[2*j], fmaf(acc[i][j][3], alv[2*j+1], el2));
                er2 = fmaf(acc[i][j][2], arv[2*j], fmaf(acc[i][j][3], arv[2*j+1], er2));
            }
#pragma unroll
            for (int o = 1; o <= 2; o <<= 1) {
                el1 += __shfl_xor_sync(0xffffffffu, el1, o);
                er1 += __shfl_xor_sync(0xffffffffu, er1, o);
                el2 += __shfl_xor_sync(0xffffffffu, el2, o);
                er2 += __shfl_xor_sync(0xffffffffu, er2, o);
            }
            if (tig == 0) {
                int r1 = bm + wm * 32 + i * 16 + grp;
                g_el[r1 * HH + hglob]       = el1;
                g_er[r1 * HH + hglob]       = er1;
                g_el[(r1 + 8) * HH + hglob] = el2;
                g_er[(r1 + 8) * HH + hglob] = er2;
            }
            wmax = fmaxf(wmax, fmaxf(el1, el2));
        }
#pragma unroll
        for (int o = 16; o >= 4; o >>= 1)
            wmax = fmaxf(wmax, __shfl_xor_sync(0xffffffffu, wmax, o));
        if (lane == 0) atomicMax(&elmaxU[hglob], fenc(wmax));
    }
}

// ---------------- per-node edge-softmax aggregation (warp per node, bf16 gather) ----------------
__global__ __launch_bounds__(256) void agg_kernel(const __nv_bfloat16* __restrict__ zb,
                                                  const float* __restrict__ hprev,
                                                  float* __restrict__ hout,
                                                  const unsigned* __restrict__ elmaxU,
                                                  int residual, int emit_bf16) {
    int n    = (blockIdx.x * blockDim.x + threadIdx.x) >> 5;
    int lane = threadIdx.x & 31;
    if (n >= NN) return;

    int base = g_rowptr[n];
    int deg  = g_rowptr[n + 1] - base;
    float4 er4 = ((const float4*)g_er)[n];
    uint4 Me = *(const uint4*)elmaxU;
    float m0 = lrelu(fdec(Me.x) + er4.x), m1 = lrelu(fdec(Me.y) + er4.y);
    float m2 = lrelu(fdec(Me.z) + er4.z), m3 = lrelu(fdec(Me.w) + er4.w);

    int hh = lane >> 3;

    float acc0 = 0.f, acc1 = 0.f, acc2 = 0.f, acc3 = 0.f;
    float acc4 = 0.f, acc5 = 0.f, acc6 = 0.f, acc7 = 0.f;
    float ssum = 0.f;

    for (int c = 0; c < deg; c += 32) {
        int rem = deg - c; if (rem > 32) rem = 32;
        int    s_l = 0;
        float4 w4  = {0.f, 0.f, 0.f, 0.f};
        if (lane < rem) {
            s_l = g_esrc[base + c + lane];
            float4 e4 = ((const float4*)g_el)[s_l];
            w4.x = __expf(lrelu(e4.x + er4.x) - m0);
            w4.y = __expf(lrelu(e4.y + er4.y) - m1);
            w4.z = __expf(lrelu(e4.z + er4.z) - m2);
            w4.w = __expf(lrelu(e4.w + er4.w) - m3);
        }
#pragma unroll 4
        for (int k = 0; k < rem; k++) {
            int   s  = __shfl_sync(0xffffffffu, s_l, k);
            float wx = __shfl_sync(0xffffffffu, w4.x, k);
            float wy = __shfl_sync(0xffffffffu, w4.y, k);
            float wz = __shfl_sync(0xffffffffu, w4.z, k);
            float ww = __shfl_sync(0xffffffffu, w4.w, k);
            float w  = (hh == 0) ? wx : (hh == 1) ? wy : (hh == 2) ? wz : ww;
            ssum += w;
            uint4 p = *(const uint4*)(zb + (size_t)s * HD + lane * 8);
            float2 f0 = __bfloat1622float2(*(__nv_bfloat162*)&p.x);
            float2 f1 = __bfloat1622float2(*(__nv_bfloat162*)&p.y);
            float2 f2 = __bfloat1622float2(*(__nv_bfloat162*)&p.z);
            float2 f3 = __bfloat1622float2(*(__nv_bfloat162*)&p.w);
            acc0 = fmaf(w, f0.x, acc0); acc1 = fmaf(w, f0.y, acc1);
            acc2 = fmaf(w, f1.x, acc2); acc3 = fmaf(w, f1.y, acc3);
            acc4 = fmaf(w, f2.x, acc4); acc5 = fmaf(w, f2.y, acc5);
            acc6 = fmaf(w, f3.x, acc6); acc7 = fmaf(w, f3.y, acc7);
        }
    }

    float inv = 1.f / ssum;
    float o8[8] = {acc0*inv, acc1*inv, acc2*inv, acc3*inv,
                   acc4*inv, acc5*inv, acc6*inv, acc7*inv};
    size_t ob = (size_t)n * HD + lane * 8;
    if (residual) {
        const float4* pp = (const float4*)(hprev + ob);
        float4 p0 = pp[0], p1 = pp[1];
        float pr[8] = {p0.x, p0.y, p0.z, p0.w, p1.x, p1.y, p1.z, p1.w};
#pragma unroll
        for (int i = 0; i < 8; i++) o8[i] = elu1(o8[i] + pr[i]);
    }
#pragma unroll
    for (int i = 0; i < 8; i++) o8[i] = elu1(o8[i]);
    float4 v0 = {o8[0], o8[1], o8[2], o8[3]};
    float4 v1 = {o8[4], o8[5], o8[6], o8[7]};
    *(float4*)(hout + ob)     = v0;
    *(float4*)(hout + ob + 4) = v1;

    if (emit_bf16) {
        __nv_bfloat16 hhi[8], hlo[8];
#pragma unroll
        for (int i = 0; i < 8; i++) {
            hhi[i] = __float2bfloat16(o8[i]);
            hlo[i] = __float2bfloat16(o8[i] - __bfloat162float(hhi[i]));
        }
        *(uint4*)(g_ahi + ob) = *(uint4*)hhi;
        *(uint4*)(g_alo + ob) = *(uint4*)hlo;
    }
}

// ---------------- pooling + classifier ----------------
__global__ __launch_bounds__(256) void pool_kernel(const float* __restrict__ h,
                                                   const float* __restrict__ Wc,
                                                   const float* __restrict__ bc,
                                                   float* __restrict__ out) {
    __shared__ float hg[HD];
    int g = blockIdx.x;
    int t = threadIdx.x;
    float s = 0.f;
    const float* base = h + (size_t)g * NPG * HD + t;
    for (int i = 0; i < NPG; i++) s += base[(size_t)i * HD];
    hg[t] = elu1(s * (1.f / NPG));
    __syncthreads();
    if (t < CC) {
        float acc = bc[t];
        for (int f = 0; f < HD; f++) acc = fmaf(hg[f], Wc[f * CC + t], acc);
        out[g * CC + t] = acc;
    }
}

// ---------------- launch ----------------
extern "C" void kernel_launch(void* const* d_in, const int* in_sizes, int n_in,
                              void* d_out, int out_size) {
    const float* x   = (const float*)d_in[0];
    const int*   src = (const int*)  d_in[1];
    const int*   dst = (const int*)  d_in[2];
    const float* W0  = (const float*)d_in[4];
    const float* al0 = (const float*)d_in[5];
    const float* ar0 = (const float*)d_in[6];
    const float* W1  = (const float*)d_in[7];
    const float* al1 = (const float*)d_in[8];
    const float* ar1 = (const float*)d_in[9];
    const float* W2  = (const float*)d_in[10];
    const float* al2 = (const float*)d_in[11];
    const float* ar2 = (const float*)d_in[12];
    const float* Wc  = (const float*)d_in[13];
    const float* bc  = (const float*)d_in[14];
    float* out = (float*)d_out;

    float *hA, *hB;
    __nv_bfloat16 *zb, *ahi, *alo, *bhi, *blo;
    unsigned* emx;
    cudaGetSymbolAddress((void**)&zb,  g_zb);
    cudaGetSymbolAddress((void**)&hA,  g_hA);
    cudaGetSymbolAddress((void**)&hB,  g_hB);
    cudaGetSymbolAddress((void**)&ahi, g_ahi);
    cudaGetSymbolAddress((void**)&alo, g_alo);
    cudaGetSymbolAddress((void**)&bhi, g_bhi);
    cudaGetSymbolAddress((void**)&blo, g_blo);
    cudaGetSymbolAddress((void**)&emx, g_elmaxU);

    cudaFuncSetAttribute(gemm_mma_kernel,
                         cudaFuncAttributeMaxDynamicSharedMemorySize, SMEM_GEMM);

    // fork CSR build onto a side stream, overlapped with conv + layer-0 GEMM
    cudaStream_t s2;
    cudaStreamCreateWithFlags(&s2, cudaStreamNonBlocking);
    cudaEvent_t evFork, evJoin;
    cudaEventCreateWithFlags(&evFork, cudaEventDisableTiming);
    cudaEventCreateWithFlags(&evJoin, cudaEventDisableTiming);

    cudaEventRecord(evFork, 0);
    cudaStreamWaitEvent(s2, evFork, 0);
    zero_deg_kernel<<<(NN + 255) / 256, 256, 0, s2>>>();
    hist_kernel<<<(EE + 255) / 256, 256, 0, s2>>>(dst);
    scan_kernel<<<1, 512, 0, s2>>>();
    scatter_kernel<<<(EE + 255) / 256, 256, 0, s2>>>(src, dst);
    cudaEventRecord(evJoin, s2);

    // main stream: conversions (convB also resets elmax) + layer-0 GEMM
    convB_kernel<<<((128 + 512) * HD + 255) / 256, 256>>>(W0, W1, W2);
    convA_kernel<<<(NN * 128 / 4 + 255) / 256, 256>>>(x, NN * 128 / 4);

    dim3 ggrid(NN / 128, 2);
    gemm_mma_kernel<<<ggrid, 256, SMEM_GEMM>>>(ahi, alo, bhi, blo, zb,
                                               emx + 0, al0, ar0, 128);
    cudaStreamWaitEvent(0, evJoin, 0);   // CSR ready before first agg
    agg_kernel<<<NN / 8, 256>>>(zb, nullptr, hA, emx + 0, 0, 1);

    // layer 1
    gemm_mma_kernel<<<ggrid, 256, SMEM_GEMM>>>(ahi, alo, bhi + HD * HD, blo + HD * HD,
                                               zb, emx + 4, al1, ar1, 256);
    agg_kernel<<<NN / 8, 256>>>(zb, hA, hB, emx + 4, 1, 1);

    // layer 2
    gemm_mma_kernel<<<ggrid, 256, SMEM_GEMM>>>(ahi, alo, bhi + 2 * HD * HD, blo + 2 * HD * HD,
                                               zb, emx + 8, al2, ar2, 256);
    agg_kernel<<<NN / 8, 256>>>(zb, hB, hA, emx + 8, 1, 0);

    pool_kernel<<<GG, 256>>>(hA, Wc, bc, out);
}

// round 9
// speedup vs baseline: 2.0580x; 1.1764x over previous
#include <cuda_runtime.h>
#include <cuda_bf16.h>
#include <cuda_fp16.h>
#include <math.h>
#include <stdint.h>

#define NN 20480
#define EE 327680
#define GG 64
#define HD 256     // H*D
#define HH 4
#define DD 64
#define CC 10
#define NPG (NN/GG)

// ---------------- scratch (static device globals; no allocation) ----------------
__device__ __nv_bfloat16 g_zb[NN*HD];        // z in bf16 (agg gather operand)
__device__ float g_hA[NN*HD];
__device__ float g_hB[NN*HD];
__device__ float g_el[NN*HH];
__device__ float g_er[NN*HH];
__device__ unsigned g_elmaxU[3*HH];          // encoded per-head el max, per layer
__device__ int   g_deg[NN];
__device__ int   g_rowptr[NN+1];
__device__ int   g_cursor[NN];
__device__ int   g_esrc[EE];
__device__ __half g_af16[NN*HD];             // GEMM A operand (fp16)
__device__ __half g_bf16[3][HD*HD];          // W per layer: [K][256] fp16

__device__ __forceinline__ float lrelu(float x) { return x > 0.f ? x : 0.2f * x; }
__device__ __forceinline__ float elu1 (float x) { return x > 0.f ? x : expm1f(x); }

// monotone float<->uint encoding for atomicMax on floats
__device__ __forceinline__ unsigned fenc(float f) {
    unsigned u = __float_as_uint(f);
    return (u & 0x80000000u) ? ~u : (u | 0x80000000u);
}
__device__ __forceinline__ float fdec(unsigned u) {
    return (u & 0x80000000u) ? __uint_as_float(u & 0x7fffffffu) : __uint_as_float(~u);
}
__device__ __forceinline__ unsigned h2_bits(__half2 h) {
    return *reinterpret_cast<unsigned*>(&h);
}

__device__ __forceinline__ uint32_t smem_u32(const void* p) {
    uint32_t a;
    asm("{ .reg .u64 t; cvta.to.shared.u64 t, %1; cvt.u32.u64 %0, t; }" : "=r"(a) : "l"(p));
    return a;
}
__device__ __forceinline__ void ldmat4(uint32_t* r, uint32_t a) {
    asm volatile("ldmatrix.sync.aligned.m8n8.x4.shared.b16 {%0,%1,%2,%3}, [%4];"
        : "=r"(r[0]), "=r"(r[1]), "=r"(r[2]), "=r"(r[3]) : "r"(a));
}
__device__ __forceinline__ void ldmat4t(uint32_t* r, uint32_t a) {
    asm volatile("ldmatrix.sync.aligned.m8n8.x4.trans.shared.b16 {%0,%1,%2,%3}, [%4];"
        : "=r"(r[0]), "=r"(r[1]), "=r"(r[2]), "=r"(r[3]) : "r"(a));
}
__device__ __forceinline__ void mma16816h(float* c, const uint32_t* a, const uint32_t* b) {
    asm volatile(
        "mma.sync.aligned.m16n8k16.row.col.f32.f16.f16.f32 "
        "{%0,%1,%2,%3}, {%4,%5,%6,%7}, {%8,%9}, {%0,%1,%2,%3};"
        : "+f"(c[0]), "+f"(c[1]), "+f"(c[2]), "+f"(c[3])
        : "r"(a[0]), "r"(a[1]), "r"(a[2]), "r"(a[3]), "r"(b[0]), "r"(b[1]));
}
#define CP16(s, g) asm volatile("cp.async.cg.shared.global [%0], [%1], 16;" \
    :: "r"(s), "l"(__cvta_generic_to_global(g)))
#define CP_COMMIT() asm volatile("cp.async.commit_group;" ::: "memory")
#define CP_WAIT0()  asm volatile("cp.async.wait_group 0;" ::: "memory")
#define CP_WAIT1()  asm volatile("cp.async.wait_group 1;" ::: "memory")

// ---------------- CSR build ----------------
__global__ void zero_deg_kernel() {
    int i = blockIdx.x * blockDim.x + threadIdx.x;
    if (i < NN) g_deg[i] = 0;
}
__global__ void hist_kernel(const int* __restrict__ dst) {
    int i = blockIdx.x * blockDim.x + threadIdx.x;
    if (i < EE) atomicAdd(&g_deg[dst[i]], 1);
}
__global__ void scan_kernel() {
    __shared__ int part[512];
    const int CH = NN / 512;
    int t = threadIdx.x;
    int s = 0;
    for (int i = 0; i < CH; i++) s += g_deg[t*CH + i];
    part[t] = s;
    __syncthreads();
    if (t == 0) {
        int r = 0;
        for (int i = 0; i < 512; i++) { int v = part[i]; part[i] = r; r += v; }
        g_rowptr[NN] = r;
    }
    __syncthreads();
    int run = part[t];
    for (int i = 0; i < CH; i++) {
        int idx = t*CH + i;
        g_rowptr[idx] = run;
        g_cursor[idx] = run;
        run += g_deg[idx];
    }
}
__global__ void scatter_kernel(const int* __restrict__ src, const int* __restrict__ dst) {
    int i = blockIdx.x * blockDim.x + threadIdx.x;
    if (i < EE) {
        int p = atomicAdd(&g_cursor[dst[i]], 1);
        g_esrc[p] = src[i];
    }
}

// ---------------- fp32 -> fp16 (layer-0 input only) ----------------
__global__ void convA_kernel(const float* __restrict__ A, int n4) {
    int i = blockIdx.x * blockDim.x + threadIdx.x;
    if (i >= n4) return;
    float4 v = ((const float4*)A)[i];
    __half2 h0 = __floats2half2_rn(v.x, v.y);
    __half2 h1 = __floats2half2_rn(v.z, v.w);
    ((__half2*)g_af16)[2*i]   = h0;
    ((__half2*)g_af16)[2*i+1] = h1;
}
// all three weight matrices in one launch; also resets elmax buffers (per replay)
__global__ void convB_kernel(const float* __restrict__ W0,
                             const float* __restrict__ W1,
                             const float* __restrict__ W2) {
    int i = blockIdx.x * blockDim.x + threadIdx.x;
    if (blockIdx.x == 0 && threadIdx.x < 3 * HH) g_elmaxU[threadIdx.x] = 0u;
    const float* B; int layer, off;
    if (i < 128 * HD)           { B = W0; layer = 0; off = i; }
    else if (i < (128+256)*HD)  { B = W1; layer = 1; off = i - 128 * HD; }
    else if (i < (128+512)*HD)  { B = W2; layer = 2; off = i - (128+256) * HD; }
    else return;
    g_bf16[layer][off] = __float2half(B[off]);
}

// ---------------- fp16 mma.sync GEMM + fused attn projections + fused el-max ----------------
// CTA 128(M)x128(N), 8 warps (warp = 32x64), K chunks of 32, cp.async double buffer.
#define ARB 80        // A smem row bytes (32 fp16 = 64B + pad)
#define BRB 272       // B smem row bytes (128 fp16 = 256B + pad)
#define S_B   10240
#define BUF   18944
#define SMEM_GEMM (2*BUF)

__global__ __launch_bounds__(256, 2) void gemm_mma_kernel(
    const __half* __restrict__ A, const __half* __restrict__ B,
    __nv_bfloat16* __restrict__ Zb, unsigned* __restrict__ elmaxU,
    const float* __restrict__ al, const float* __restrict__ ar, int K) {
    extern __shared__ char sm[];
    uint32_t sb = smem_u32(sm);
    int tid = threadIdx.x, lane = tid & 31, wid = tid >> 5;
    int wm = wid & 3, wn = wid >> 2;
    int bm = blockIdx.x * 128, bn = blockIdx.y * 128;

    float acc[2][8][4];
#pragma unroll
    for (int i = 0; i < 2; i++)
#pragma unroll
        for (int j = 0; j < 8; j++)
#pragma unroll
            for (int q = 0; q < 4; q++) acc[i][j][q] = 0.f;

    auto issue = [&](int c, int buf) {
        int k0 = c * 32;
        uint32_t s0 = sb + buf * BUF;
#pragma unroll
        for (int r = 0; r < 2; r++) {
            int idx  = tid + r * 256;
            int arow = idx >> 2, ach = idx & 3;
            const __half* ga = A + (size_t)(bm + arow) * K + k0 + ach * 8;
            CP16(s0 + arow * ARB + ach * 16, ga);
        }
#pragma unroll
        for (int r = 0; r < 2; r++) {
            int idx  = tid + r * 256;
            int brow = idx >> 4, bch = idx & 15;
            const __half* gb = B + (size_t)(k0 + brow) * HD + bn + bch * 8;
            CP16(s0 + S_B + brow * BRB + bch * 16, gb);
        }
    };

    auto compute = [&](int buf) {
        uint32_t s0 = sb + buf * BUF;
#pragma unroll
        for (int ks = 0; ks < 32; ks += 16) {
            uint32_t ah[2][4];
#pragma unroll
            for (int i = 0; i < 2; i++) {
                int row = wm * 32 + i * 16 + (lane & 15);
                uint32_t ad = s0 + row * ARB + (ks + (lane >> 4) * 8) * 2;
                ldmat4(ah[i], ad);
            }
#pragma unroll
            for (int jj = 0; jj < 4; jj++) {
                int krow = ks + (lane & 15);
                int ncol = wn * 64 + jj * 16 + (lane >> 4) * 8;
                uint32_t bd = s0 + S_B + krow * BRB + ncol * 2;
                uint32_t bh[4];
                ldmat4t(bh, bd);
#pragma unroll
                for (int i = 0; i < 2; i++) {
                    mma16816h(acc[i][2*jj],   ah[i], bh);
                    mma16816h(acc[i][2*jj+1], ah[i], bh + 2);
                }
            }
        }
    };

    int nch = K >> 5;
    issue(0, 0);
    CP_COMMIT();
    for (int c = 0; c < nch; c++) {
        if (c + 1 < nch) {
            issue(c + 1, (c + 1) & 1);
            CP_COMMIT();
            CP_WAIT1();
        } else {
            CP_WAIT0();
        }
        __syncthreads();
        compute(c & 1);
        __syncthreads();
    }

    int grp = lane >> 2, tig = lane & 3;

    // ---- store z as bf16 ----
#pragma unroll
    for (int i = 0; i < 2; i++) {
        int rbase = bm + wm * 32 + i * 16 + grp;
#pragma unroll
        for (int j = 0; j < 8; j++) {
            int col = bn + wn * 64 + j * 8 + tig * 2;
            __nv_bfloat162 b0 = __floats2bfloat162_rn(acc[i][j][0], acc[i][j][1]);
            __nv_bfloat162 b1 = __floats2bfloat162_rn(acc[i][j][2], acc[i][j][3]);
            *(__nv_bfloat162*)(Zb + (size_t)rbase * HD + col)       = b0;
            *(__nv_bfloat162*)(Zb + (size_t)(rbase + 8) * HD + col) = b1;
        }
    }

    {   // ---- fused el/er for head hglob + global el-max atomic ----
        int hglob = (bn >> 6) + wn;
        const float* alh = al + hglob * DD;
        const float* arh = ar + hglob * DD;
        float alv[16], arv[16];
#pragma unroll
        for (int j = 0; j < 8; j++) {
            int cw = j * 8 + tig * 2;
            alv[2*j]   = alh[cw];   alv[2*j+1] = alh[cw+1];
            arv[2*j]   = arh[cw];   arv[2*j+1] = arh[cw+1];
        }
        float wmax = -1e30f;
#pragma unroll
        for (int i = 0; i < 2; i++) {
            float el1 = 0.f, er1 = 0.f, el2 = 0.f, er2 = 0.f;
#pragma unroll
            for (int j = 0; j < 8; j++) {
                el1 = fmaf(acc[i][j][0], alv[2*j], fmaf(acc[i][j][1], alv[2*j+1], el1));
                er1 = fmaf(acc[i][j][0], arv[2*j], fmaf(acc[i][j][1], arv[2*j+1], er1));
                el2 = fmaf(acc[i][j][2], alv[2*j], fmaf(acc[i][j][3], alv[2*j+1], el2));
                er2 = fmaf(acc[i][j][2], arv[2*j], fmaf(acc[i][j][3], arv[2*j+1], er2));
            }
#pragma unroll
            for (int o = 1; o <= 2; o <<= 1) {
                el1 += __shfl_xor_sync(0xffffffffu, el1, o);
                er1 += __shfl_xor_sync(0xffffffffu, er1, o);
                el2 += __shfl_xor_sync(0xffffffffu, el2, o);
                er2 += __shfl_xor_sync(0xffffffffu, er2, o);
            }
            if (tig == 0) {
                int r1 = bm + wm * 32 + i * 16 + grp;
                g_el[r1 * HH + hglob]       = el1;
                g_er[r1 * HH + hglob]       = er1;
                g_el[(r1 + 8) * HH + hglob] = el2;
                g_er[(r1 + 8) * HH + hglob] = er2;
            }
            wmax = fmaxf(wmax, fmaxf(el1, el2));
        }
#pragma unroll
        for (int o = 16; o >= 4; o >>= 1)
            wmax = fmaxf(wmax, __shfl_xor_sync(0xffffffffu, wmax, o));
        if (lane == 0) atomicMax(&elmaxU[hglob], fenc(wmax));
    }
}

// ---------------- per-node edge-softmax aggregation (warp per node, bf16 gather) ----------------
__global__ __launch_bounds__(256) void agg_kernel(const __nv_bfloat16* __restrict__ zb,
                                                  const float* __restrict__ hprev,
                                                  float* __restrict__ hout,
                                                  const unsigned* __restrict__ elmaxU,
                                                  int residual, int emit_f16) {
    int n    = (blockIdx.x * blockDim.x + threadIdx.x) >> 5;
    int lane = threadIdx.x & 31;
    if (n >= NN) return;

    int base = g_rowptr[n];
    int deg  = g_rowptr[n + 1] - base;
    float4 er4 = ((const float4*)g_er)[n];
    uint4 Me = *(const uint4*)elmaxU;
    float m0 = lrelu(fdec(Me.x) + er4.x), m1 = lrelu(fdec(Me.y) + er4.y);
    float m2 = lrelu(fdec(Me.z) + er4.z), m3 = lrelu(fdec(Me.w) + er4.w);

    int hh = lane >> 3;

    float acc0 = 0.f, acc1 = 0.f, acc2 = 0.f, acc3 = 0.f;
    float acc4 = 0.f, acc5 = 0.f, acc6 = 0.f, acc7 = 0.f;
    float ssum = 0.f;

    for (int c = 0; c < deg; c += 32) {
        int rem = deg - c; if (rem > 32) rem = 32;
        int    s_l = 0;
        float4 w4  = {0.f, 0.f, 0.f, 0.f};
        if (lane < rem) {
            s_l = g_esrc[base + c + lane];
            float4 e4 = ((const float4*)g_el)[s_l];
            w4.x = __expf(lrelu(e4.x + er4.x) - m0);
            w4.y = __expf(lrelu(e4.y + er4.y) - m1);
            w4.z = __expf(lrelu(e4.z + er4.z) - m2);
            w4.w = __expf(lrelu(e4.w + er4.w) - m3);
        }
#pragma unroll 4
        for (int k = 0; k < rem; k++) {
            int   s  = __shfl_sync(0xffffffffu, s_l, k);
            float wx = __shfl_sync(0xffffffffu, w4.x, k);
            float wy = __shfl_sync(0xffffffffu, w4.y, k);
            float wz = __shfl_sync(0xffffffffu, w4.z, k);
            float ww = __shfl_sync(0xffffffffu, w4.w, k);
            float w  = (hh == 0) ? wx : (hh == 1) ? wy : (hh == 2) ? wz : ww;
            ssum += w;
            uint4 p = *(const uint4*)(zb + (size_t)s * HD + lane * 8);
            float2 f0 = __bfloat1622float2(*(__nv_bfloat162*)&p.x);
            float2 f1 = __bfloat1622float2(*(__nv_bfloat162*)&p.y);
            float2 f2 = __bfloat1622float2(*(__nv_bfloat162*)&p.z);
            float2 f3 = __bfloat1622float2(*(__nv_bfloat162*)&p.w);
            acc0 = fmaf(w, f0.x, acc0); acc1 = fmaf(w, f0.y, acc1);
            acc2 = fmaf(w, f1.x, acc2); acc3 = fmaf(w, f1.y, acc3);
            acc4 = fmaf(w, f2.x, acc4); acc5 = fmaf(w, f2.y, acc5);
            acc6 = fmaf(w, f3.x, acc6); acc7 = fmaf(w, f3.y, acc7);
        }
    }

    float inv = 1.f / ssum;
    float o8[8] = {acc0*inv, acc1*inv, acc2*inv, acc3*inv,
                   acc4*inv, acc5*inv, acc6*inv, acc7*inv};
    size_t ob = (size_t)n * HD + lane * 8;
    if (residual) {
        const float4* pp = (const float4*)(hprev + ob);
        float4 p0 = pp[0], p1 = pp[1];
        float pr[8] = {p0.x, p0.y, p0.z, p0.w, p1.x, p1.y, p1.z, p1.w};
#pragma unroll
        for (int i = 0; i < 8; i++) o8[i] = elu1(o8[i] + pr[i]);
    }
#pragma unroll
    for (int i = 0; i < 8; i++) o8[i] = elu1(o8[i]);
    float4 v0 = {o8[0], o8[1], o8[2], o8[3]};
    float4 v1 = {o8[4], o8[5], o8[6], o8[7]};
    *(float4*)(hout + ob)     = v0;
    *(float4*)(hout + ob + 4) = v1;

    if (emit_f16) {   // next layer's GEMM A operand
        __half2 e0 = __floats2half2_rn(o8[0], o8[1]);
        __half2 e1 = __floats2half2_rn(o8[2], o8[3]);
        __half2 e2 = __floats2half2_rn(o8[4], o8[5]);
        __half2 e3 = __floats2half2_rn(o8[6], o8[7]);
        uint4 pk = {h2_bits(e0), h2_bits(e1), h2_bits(e2), h2_bits(e3)};
        *(uint4*)(g_af16 + ob) = pk;
    }
}

// ---------------- pooling + classifier ----------------
__global__ __launch_bounds__(256) void pool_kernel(const float* __restrict__ h,
                                                   const float* __restrict__ Wc,
                                                   const float* __restrict__ bc,
                                                   float* __restrict__ out) {
    __shared__ float hg[HD];
    int g = blockIdx.x;
    int t = threadIdx.x;
    float s = 0.f;
    const float* base = h + (size_t)g * NPG * HD + t;
    for (int i = 0; i < NPG; i++) s += base[(size_t)i * HD];
    hg[t] = elu1(s * (1.f / NPG));
    __syncthreads();
    if (t < CC) {
        float acc = bc[t];
        for (int f = 0; f < HD; f++) acc = fmaf(hg[f], Wc[f * CC + t], acc);
        out[g * CC + t] = acc;
    }
}

// ---------------- launch ----------------
extern "C" void kernel_launch(void* const* d_in, const int* in_sizes, int n_in,
                              void* d_out, int out_size) {
    const float* x   = (const float*)d_in[0];
    const int*   src = (const int*)  d_in[1];
    const int*   dst = (const int*)  d_in[2];
    const float* W0  = (const float*)d_in[4];
    const float* al0 = (const float*)d_in[5];
    const float* ar0 = (const float*)d_in[6];
    const float* W1  = (const float*)d_in[7];
    const float* al1 = (const float*)d_in[8];
    const float* ar1 = (const float*)d_in[9];
    const float* W2  = (const float*)d_in[10];
    const float* al2 = (const float*)d_in[11];
    const float* ar2 = (const float*)d_in[12];
    const float* Wc  = (const float*)d_in[13];
    const float* bc  = (const float*)d_in[14];
    float* out = (float*)d_out;

    float *hA, *hB;
    __nv_bfloat16 *zb;
    __half *af16, *bf16;
    unsigned* emx;
    cudaGetSymbolAddress((void**)&zb,   g_zb);
    cudaGetSymbolAddress((void**)&hA,   g_hA);
    cudaGetSymbolAddress((void**)&hB,   g_hB);
    cudaGetSymbolAddress((void**)&af16, g_af16);
    cudaGetSymbolAddress((void**)&bf16, g_bf16);
    cudaGetSymbolAddress((void**)&emx,  g_elmaxU);

    cudaFuncSetAttribute(gemm_mma_kernel,
                         cudaFuncAttributeMaxDynamicSharedMemorySize, SMEM_GEMM);

    // fork CSR build onto a side stream, overlapped with conv + layer-0 GEMM
    cudaStream_t s2;
    cudaStreamCreateWithFlags(&s2, cudaStreamNonBlocking);
    cudaEvent_t evFork, evJoin;
    cudaEventCreateWithFlags(&evFork, cudaEventDisableTiming);
    cudaEventCreateWithFlags(&evJoin, cudaEventDisableTiming);

    cudaEventRecord(evFork, 0);
    cudaStreamWaitEvent(s2, evFork, 0);
    zero_deg_kernel<<<(NN + 255) / 256, 256, 0, s2>>>();
    hist_kernel<<<(EE + 255) / 256, 256, 0, s2>>>(dst);
    scan_kernel<<<1, 512, 0, s2>>>();
    scatter_kernel<<<(EE + 255) / 256, 256, 0, s2>>>(src, dst);
    cudaEventRecord(evJoin, s2);

    // main stream: conversions (convB also resets elmax) + layer-0 GEMM
    convB_kernel<<<((128 + 512) * HD + 255) / 256, 256>>>(W0, W1, W2);
    convA_kernel<<<(NN * 128 / 4 + 255) / 256, 256>>>(x, NN * 128 / 4);

    dim3 ggrid(NN / 128, 2);
    gemm_mma_kernel<<<ggrid, 256, SMEM_GEMM>>>(af16, bf16, zb,
                                               emx + 0, al0, ar0, 128);
    cudaStreamWaitEvent(0, evJoin, 0);   // CSR ready before first agg
    agg_kernel<<<NN / 8, 256>>>(zb, nullptr, hA, emx + 0, 0, 1);

    // layer 1
    gemm_mma_kernel<<<ggrid, 256, SMEM_GEMM>>>(af16, bf16 + HD * HD, zb,
                                               emx + 4, al1, ar1, 256);
    agg_kernel<<<NN / 8, 256>>>(zb, hA, hB, emx + 4, 1, 1);

    // layer 2
    gemm_mma_kernel<<<ggrid, 256, SMEM_GEMM>>>(af16, bf16 + 2 * HD * HD, zb,
                                               emx + 8, al2, ar2, 256);
    agg_kernel<<<NN / 8, 256>>>(zb, hB, hA, emx + 8, 1, 0);

    pool_kernel<<<GG, 256>>>(hA, Wc, bc, out);
}

// round 10
// speedup vs baseline: 2.2337x; 1.0854x over previous
#include <cuda_runtime.h>
#include <cuda_bf16.h>
#include <cuda_fp16.h>
#include <math.h>
#include <stdint.h>

#define NN 20480
#define EE 327680
#define GG 64
#define HD 256     // H*D
#define HH 4
#define DD 64
#define CC 10
#define NPG (NN/GG)

// ---------------- scratch (static device globals; no allocation) ----------------
__device__ __nv_bfloat16 g_zb[NN*HD];        // z in bf16 (agg gather operand)
__device__ float g_hA[NN*HD];
__device__ float g_hB[NN*HD];
__device__ float g_el[NN*HH];
__device__ float g_er[NN*HH];
__device__ unsigned g_elmaxU[3*HH];          // encoded per-head el max, per layer
__device__ int   g_deg[NN];
__device__ int   g_rowptr[NN+1];
__device__ int   g_cursor[NN];
__device__ int   g_esrc[EE];
__device__ __half g_af16[NN*HD];             // GEMM A operand (fp16)
__device__ __half g_bf16[3][HD*HD];          // W per layer: [K][256] fp16

__device__ __forceinline__ float lrelu(float x) { return x > 0.f ? x : 0.2f * x; }
__device__ __forceinline__ float elu1 (float x) { return x > 0.f ? x : expm1f(x); }

// monotone float<->uint encoding for atomicMax on floats
__device__ __forceinline__ unsigned fenc(float f) {
    unsigned u = __float_as_uint(f);
    return (u & 0x80000000u) ? ~u : (u | 0x80000000u);
}
__device__ __forceinline__ float fdec(unsigned u) {
    return (u & 0x80000000u) ? __uint_as_float(u & 0x7fffffffu) : __uint_as_float(~u);
}
__device__ __forceinline__ unsigned h2_bits(__half2 h) {
    return *reinterpret_cast<unsigned*>(&h);
}
// exact bf16 pair -> two f32 (2 inst)
__device__ __forceinline__ void bf2f(unsigned r, float& lo, float& hi) {
    lo = __uint_as_float(r << 16);
    hi = __uint_as_float(r & 0xffff0000u);
}

__device__ __forceinline__ uint32_t smem_u32(const void* p) {
    uint32_t a;
    asm("{ .reg .u64 t; cvta.to.shared.u64 t, %1; cvt.u32.u64 %0, t; }" : "=r"(a) : "l"(p));
    return a;
}
__device__ __forceinline__ void ldmat4(uint32_t* r, uint32_t a) {
    asm volatile("ldmatrix.sync.aligned.m8n8.x4.shared.b16 {%0,%1,%2,%3}, [%4];"
        : "=r"(r[0]), "=r"(r[1]), "=r"(r[2]), "=r"(r[3]) : "r"(a));
}
__device__ __forceinline__ void ldmat4t(uint32_t* r, uint32_t a) {
    asm volatile("ldmatrix.sync.aligned.m8n8.x4.trans.shared.b16 {%0,%1,%2,%3}, [%4];"
        : "=r"(r[0]), "=r"(r[1]), "=r"(r[2]), "=r"(r[3]) : "r"(a));
}
__device__ __forceinline__ void mma16816h(float* c, const uint32_t* a, const uint32_t* b) {
    asm volatile(
        "mma.sync.aligned.m16n8k16.row.col.f32.f16.f16.f32 "
        "{%0,%1,%2,%3}, {%4,%5,%6,%7}, {%8,%9}, {%0,%1,%2,%3};"
        : "+f"(c[0]), "+f"(c[1]), "+f"(c[2]), "+f"(c[3])
        : "r"(a[0]), "r"(a[1]), "r"(a[2]), "r"(a[3]), "r"(b[0]), "r"(b[1]));
}
#define CP16(s, g) asm volatile("cp.async.cg.shared.global [%0], [%1], 16;" \
    :: "r"(s), "l"(__cvta_generic_to_global(g)))
#define CP_COMMIT() asm volatile("cp.async.commit_group;" ::: "memory")
#define CP_WAIT0()  asm volatile("cp.async.wait_group 0;" ::: "memory")
#define CP_WAIT1()  asm volatile("cp.async.wait_group 1;" ::: "memory")

// ---------------- CSR build ----------------
__global__ void zero_deg_kernel() {
    int i = blockIdx.x * blockDim.x + threadIdx.x;
    if (i < NN) g_deg[i] = 0;
}
__global__ void hist_kernel(const int* __restrict__ dst) {
    int i = blockIdx.x * blockDim.x + threadIdx.x;
    if (i < EE) atomicAdd(&g_deg[dst[i]], 1);
}
__global__ void scan_kernel() {
    __shared__ int part[512];
    const int CH = NN / 512;
    int t = threadIdx.x;
    int s = 0;
    for (int i = 0; i < CH; i++) s += g_deg[t*CH + i];
    part[t] = s;
    __syncthreads();
    if (t == 0) {
        int r = 0;
        for (int i = 0; i < 512; i++) { int v = part[i]; part[i] = r; r += v; }
        g_rowptr[NN] = r;
    }
    __syncthreads();
    int run = part[t];
    for (int i = 0; i < CH; i++) {
        int idx = t*CH + i;
        g_rowptr[idx] = run;
        g_cursor[idx] = run;
        run += g_deg[idx];
    }
}
__global__ void scatter_kernel(const int* __restrict__ src, const int* __restrict__ dst) {
    int i = blockIdx.x * blockDim.x + threadIdx.x;
    if (i < EE) {
        int p = atomicAdd(&g_cursor[dst[i]], 1);
        g_esrc[p] = src[i];
    }
}

// ---------------- fp32 -> fp16 (layer-0 input only) ----------------
__global__ void convA_kernel(const float* __restrict__ A, int n4) {
    int i = blockIdx.x * blockDim.x + threadIdx.x;
    if (i >= n4) return;
    float4 v = ((const float4*)A)[i];
    __half2 h0 = __floats2half2_rn(v.x, v.y);
    __half2 h1 = __floats2half2_rn(v.z, v.w);
    ((__half2*)g_af16)[2*i]   = h0;
    ((__half2*)g_af16)[2*i+1] = h1;
}
// all three weight matrices in one launch; also resets elmax buffers (per replay)
__global__ void convB_kernel(const float* __restrict__ W0,
                             const float* __restrict__ W1,
                             const float* __restrict__ W2) {
    int i = blockIdx.x * blockDim.x + threadIdx.x;
    if (blockIdx.x == 0 && threadIdx.x < 3 * HH) g_elmaxU[threadIdx.x] = 0u;
    const float* B; int layer, off;
    if (i < 128 * HD)           { B = W0; layer = 0; off = i; }
    else if (i < (128+256)*HD)  { B = W1; layer = 1; off = i - 128 * HD; }
    else if (i < (128+512)*HD)  { B = W2; layer = 2; off = i - (128+256) * HD; }
    else return;
    g_bf16[layer][off] = __float2half(B[off]);
}

// ---------------- fp16 mma.sync GEMM + fused attn projections + fused el-max ----------------
// CTA 64(M)x128(N), 8 warps (warp = 16x64), K chunks of 32, cp.async double buffer.
#define ARB 80        // A smem row bytes (32 fp16 = 64B + pad)
#define BRB 272       // B smem row bytes (128 fp16 = 256B + pad)
#define S_B   5120    // 64 rows * ARB
#define BUF   13824   // S_B + 32*BRB
#define SMEM_GEMM (2*BUF)

__global__ __launch_bounds__(256, 3) void gemm_mma_kernel(
    const __half* __restrict__ A, const __half* __restrict__ B,
    __nv_bfloat16* __restrict__ Zb, unsigned* __restrict__ elmaxU,
    const float* __restrict__ al, const float* __restrict__ ar, int K) {
    extern __shared__ char sm[];
    uint32_t sb = smem_u32(sm);
    int tid = threadIdx.x, lane = tid & 31, wid = tid >> 5;
    int wm = wid & 3, wn = wid >> 2;
    int bm = blockIdx.x * 64, bn = blockIdx.y * 128;

    float acc[8][4];
#pragma unroll
    for (int j = 0; j < 8; j++)
#pragma unroll
        for (int q = 0; q < 4; q++) acc[j][q] = 0.f;

    auto issue = [&](int c, int buf) {
        int k0 = c * 32;
        uint32_t s0 = sb + buf * BUF;
        {   // A: 64 rows x 4 chunks of 16B = 256, 1 per thread
            int arow = tid >> 2, ach = tid & 3;
            const __half* ga = A + (size_t)(bm + arow) * K + k0 + ach * 8;
            CP16(s0 + arow * ARB + ach * 16, ga);
        }
#pragma unroll
        for (int r = 0; r < 2; r++) {  // B: 32 rows x 16 chunks = 512, 2 per thread
            int idx  = tid + r * 256;
            int brow = idx >> 4, bch = idx & 15;
            const __half* gb = B + (size_t)(k0 + brow) * HD + bn + bch * 8;
            CP16(s0 + S_B + brow * BRB + bch * 16, gb);
        }
    };

    auto compute = [&](int buf) {
        uint32_t s0 = sb + buf * BUF;
#pragma unroll
        for (int ks = 0; ks < 32; ks += 16) {
            uint32_t ah[4];
            {
                int row = wm * 16 + (lane & 15);
                uint32_t ad = s0 + row * ARB + (ks + (lane >> 4) * 8) * 2;
                ldmat4(ah, ad);
            }
#pragma unroll
            for (int jj = 0; jj < 4; jj++) {
                int krow = ks + (lane & 15);
                int ncol = wn * 64 + jj * 16 + (lane >> 4) * 8;
                uint32_t bd = s0 + S_B + krow * BRB + ncol * 2;
                uint32_t bh[4];
                ldmat4t(bh, bd);
                mma16816h(acc[2*jj],   ah, bh);
                mma16816h(acc[2*jj+1], ah, bh + 2);
            }
        }
    };

    int nch = K >> 5;
    issue(0, 0);
    CP_COMMIT();
    for (int c = 0; c < nch; c++) {
        if (c + 1 < nch) {
            issue(c + 1, (c + 1) & 1);
            CP_COMMIT();
            CP_WAIT1();
        } else {
            CP_WAIT0();
        }
        __syncthreads();
        compute(c & 1);
        __syncthreads();
    }

    int grp = lane >> 2, tig = lane & 3;

    // ---- store z as bf16 (rows bm+wm*16+grp and +8) ----
    {
        int rbase = bm + wm * 16 + grp;
#pragma unroll
        for (int j = 0; j < 8; j++) {
            int col = bn + wn * 64 + j * 8 + tig * 2;
            __nv_bfloat162 b0 = __floats2bfloat162_rn(acc[j][0], acc[j][1]);
            __nv_bfloat162 b1 = __floats2bfloat162_rn(acc[j][2], acc[j][3]);
            *(__nv_bfloat162*)(Zb + (size_t)rbase * HD + col)       = b0;
            *(__nv_bfloat162*)(Zb + (size_t)(rbase + 8) * HD + col) = b1;
        }
    }

    {   // ---- fused el/er for head hglob + global el-max atomic ----
        int hglob = (bn >> 6) + wn;
        const float* alh = al + hglob * DD;
        const float* arh = ar + hglob * DD;
        float alv[16], arv[16];
#pragma unroll
        for (int j = 0; j < 8; j++) {
            int cw = j * 8 + tig * 2;
            alv[2*j]   = alh[cw];   alv[2*j+1] = alh[cw+1];
            arv[2*j]   = arh[cw];   arv[2*j+1] = arh[cw+1];
        }
        float el1 = 0.f, er1 = 0.f, el2 = 0.f, er2 = 0.f;
#pragma unroll
        for (int j = 0; j < 8; j++) {
            el1 = fmaf(acc[j][0], alv[2*j], fmaf(acc[j][1], alv[2*j+1], el1));
            er1 = fmaf(acc[j][0], arv[2*j], fmaf(acc[j][1], arv[2*j+1], er1));
            el2 = fmaf(acc[j][2], alv[2*j], fmaf(acc[j][3], alv[2*j+1], el2));
            er2 = fmaf(acc[j][2], arv[2*j], fmaf(acc[j][3], arv[2*j+1], er2));
        }
#pragma unroll
        for (int o = 1; o <= 2; o <<= 1) {
            el1 += __shfl_xor_sync(0xffffffffu, el1, o);
            er1 += __shfl_xor_sync(0xffffffffu, er1, o);
            el2 += __shfl_xor_sync(0xffffffffu, el2, o);
            er2 += __shfl_xor_sync(0xffffffffu, er2, o);
        }
        if (tig == 0) {
            int r1 = bm + wm * 16 + grp;
            g_el[r1 * HH + hglob]       = el1;
            g_er[r1 * HH + hglob]       = er1;
            g_el[(r1 + 8) * HH + hglob] = el2;
            g_er[(r1 + 8) * HH + hglob] = er2;
        }
        float wmax = fmaxf(el1, el2);
#pragma unroll
        for (int o = 16; o >= 4; o >>= 1)
            wmax = fmaxf(wmax, __shfl_xor_sync(0xffffffffu, wmax, o));
        if (lane == 0) atomicMax(&elmaxU[hglob], fenc(wmax));
    }
}

// ---------------- per-node edge-softmax aggregation ----------------
// 2 nodes per warp; each half-warp (16 lanes) handles one node, lane owns 16 features.
__global__ __launch_bounds__(256) void agg_kernel(const __nv_bfloat16* __restrict__ zb,
                                                  const float* __restrict__ hprev,
                                                  float* __restrict__ hout,
                                                  const unsigned* __restrict__ elmaxU,
                                                  int residual, int emit_f16) {
    int gw   = (blockIdx.x * blockDim.x + threadIdx.x) >> 5;
    int lane = threadIdx.x & 31;
    int half = lane >> 4;
    int hl   = lane & 15;
    int n    = gw * 2 + half;
    if (n >= NN) return;
    unsigned hmask = 0xFFFFu << (half * 16);

    int base = g_rowptr[n];
    int deg  = g_rowptr[n + 1] - base;
    float4 er4 = ((const float4*)g_er)[n];
    uint4 Me = *(const uint4*)elmaxU;
    float m0 = lrelu(fdec(Me.x) + er4.x), m1 = lrelu(fdec(Me.y) + er4.y);
    float m2 = lrelu(fdec(Me.z) + er4.z), m3 = lrelu(fdec(Me.w) + er4.w);

    int hh = hl >> 2;    // lane owns features hl*16..hl*16+15 -> head = hl/4

    float acc[16];
#pragma unroll
    for (int i = 0; i < 16; i++) acc[i] = 0.f;
    float ssum = 0.f;

    for (int c = 0; c < deg; c += 16) {
        int rem = deg - c; if (rem > 16) rem = 16;
        int      s_l  = 0;
        unsigned wp01 = 0, wp23 = 0;
        if (hl < rem) {
            s_l = g_esrc[base + c + hl];
            float4 e4 = ((const float4*)g_el)[s_l];
            float wx = __expf(lrelu(e4.x + er4.x) - m0);
            float wy = __expf(lrelu(e4.y + er4.y) - m1);
            float wz = __expf(lrelu(e4.z + er4.z) - m2);
            float ww = __expf(lrelu(e4.w + er4.w) - m3);
            wp01 = h2_bits(__floats2half2_rn(wx, wy));
            wp23 = h2_bits(__floats2half2_rn(wz, ww));
        }
#pragma unroll 4
        for (int k = 0; k < rem; k++) {
            int      s  = __shfl_sync(hmask, s_l,  k, 16);
            unsigned a0 = __shfl_sync(hmask, wp01, k, 16);
            unsigned a1 = __shfl_sync(hmask, wp23, k, 16);
            unsigned wp = (hh < 2) ? a0 : a1;
            __half2  h2 = *reinterpret_cast<__half2*>(&wp);
            float w = (hh & 1) ? __high2float(h2) : __low2float(h2);
            ssum += w;
            const uint4* zr = (const uint4*)(zb + (size_t)s * HD + hl * 16);
            uint4 p0 = zr[0], p1 = zr[1];
            float f0, f1, f2, f3, f4, f5, f6, f7;
            bf2f(p0.x, f0, f1); bf2f(p0.y, f2, f3);
            bf2f(p0.z, f4, f5); bf2f(p0.w, f6, f7);
            acc[0] = fmaf(w, f0, acc[0]);  acc[1] = fmaf(w, f1, acc[1]);
            acc[2] = fmaf(w, f2, acc[2]);  acc[3] = fmaf(w, f3, acc[3]);
            acc[4] = fmaf(w, f4, acc[4]);  acc[5] = fmaf(w, f5, acc[5]);
            acc[6] = fmaf(w, f6, acc[6]);  acc[7] = fmaf(w, f7, acc[7]);
            bf2f(p1.x, f0, f1); bf2f(p1.y, f2, f3);
            bf2f(p1.z, f4, f5); bf2f(p1.w, f6, f7);
            acc[8]  = fmaf(w, f0, acc[8]);  acc[9]  = fmaf(w, f1, acc[9]);
            acc[10] = fmaf(w, f2, acc[10]); acc[11] = fmaf(w, f3, acc[11]);
            acc[12] = fmaf(w, f4, acc[12]); acc[13] = fmaf(w, f5, acc[13]);
            acc[14] = fmaf(w, f6, acc[14]); acc[15] = fmaf(w, f7, acc[15]);
        }
    }

    float inv = 1.f / ssum;
    float o16[16];
#pragma unroll
    for (int i = 0; i < 16; i++) o16[i] = acc[i] * inv;
    size_t ob = (size_t)n * HD + hl * 16;
    if (residual) {
        const float4* pp = (const float4*)(hprev + ob);
#pragma unroll
        for (int q = 0; q < 4; q++) {
            float4 p = pp[q];
            o16[4*q+0] = elu1(o16[4*q+0] + p.x);
            o16[4*q+1] = elu1(o16[4*q+1] + p.y);
            o16[4*q+2] = elu1(o16[4*q+2] + p.z);
            o16[4*q+3] = elu1(o16[4*q+3] + p.w);
        }
    }
#pragma unroll
    for (int i = 0; i < 16; i++) o16[i] = elu1(o16[i]);
#pragma unroll
    for (int q = 0; q < 4; q++) {
        float4 v = {o16[4*q], o16[4*q+1], o16[4*q+2], o16[4*q+3]};
        *(float4*)(hout + ob + 4*q) = v;
    }

    if (emit_f16) {   // next layer's GEMM A operand
        uint4 pk0, pk1;
        __half2 e;
        e = __floats2half2_rn(o16[0],  o16[1]);  pk0.x = h2_bits(e);
        e = __floats2half2_rn(o16[2],  o16[3]);  pk0.y = h2_bits(e);
        e = __floats2half2_rn(o16[4],  o16[5]);  pk0.z = h2_bits(e);
        e = __floats2half2_rn(o16[6],  o16[7]);  pk0.w = h2_bits(e);
        e = __floats2half2_rn(o16[8],  o16[9]);  pk1.x = h2_bits(e);
        e = __floats2half2_rn(o16[10], o16[11]); pk1.y = h2_bits(e);
        e = __floats2half2_rn(o16[12], o16[13]); pk1.z = h2_bits(e);
        e = __floats2half2_rn(o16[14], o16[15]); pk1.w = h2_bits(e);
        *(uint4*)(g_af16 + ob)     = pk0;
        *(uint4*)(g_af16 + ob + 8) = pk1;
    }
}

// ---------------- pooling + classifier ----------------
__global__ __launch_bounds__(256) void pool_kernel(const float* __restrict__ h,
                                                   const float* __restrict__ Wc,
                                                   const float* __restrict__ bc,
                                                   float* __restrict__ out) {
    __shared__ float hg[HD];
    int g = blockIdx.x;
    int t = threadIdx.x;
    float s = 0.f;
    const float* base = h + (size_t)g * NPG * HD + t;
    for (int i = 0; i < NPG; i++) s += base[(size_t)i * HD];
    hg[t] = elu1(s * (1.f / NPG));
    __syncthreads();
    if (t < CC) {
        float acc = bc[t];
        for (int f = 0; f < HD; f++) acc = fmaf(hg[f], Wc[f * CC + t], acc);
        out[g * CC + t] = acc;
    }
}

// ---------------- launch ----------------
extern "C" void kernel_launch(void* const* d_in, const int* in_sizes, int n_in,
                              void* d_out, int out_size) {
    const float* x   = (const float*)d_in[0];
    const int*   src = (const int*)  d_in[1];
    const int*   dst = (const int*)  d_in[2];
    const float* W0  = (const float*)d_in[4];
    const float* al0 = (const float*)d_in[5];
    const float* ar0 = (const float*)d_in[6];
    const float* W1  = (const float*)d_in[7];
    const float* al1 = (const float*)d_in[8];
    const float* ar1 = (const float*)d_in[9];
    const float* W2  = (const float*)d_in[10];
    const float* al2 = (const float*)d_in[11];
    const float* ar2 = (const float*)d_in[12];
    const float* Wc  = (const float*)d_in[13];
    const float* bc  = (const float*)d_in[14];
    float* out = (float*)d_out;

    float *hA, *hB;
    __nv_bfloat16 *zb;
    __half *af16, *bf16;
    unsigned* emx;
    cudaGetSymbolAddress((void**)&zb,   g_zb);
    cudaGetSymbolAddress((void**)&hA,   g_hA);
    cudaGetSymbolAddress((void**)&hB,   g_hB);
    cudaGetSymbolAddress((void**)&af16, g_af16);
    cudaGetSymbolAddress((void**)&bf16, g_bf16);
    cudaGetSymbolAddress((void**)&emx,  g_elmaxU);

    cudaFuncSetAttribute(gemm_mma_kernel,
                         cudaFuncAttributeMaxDynamicSharedMemorySize, SMEM_GEMM);

    // fork CSR build onto a side stream, overlapped with conv + layer-0 GEMM
    cudaStream_t s2;
    cudaStreamCreateWithFlags(&s2, cudaStreamNonBlocking);
    cudaEvent_t evFork, evJoin;
    cudaEventCreateWithFlags(&evFork, cudaEventDisableTiming);
    cudaEventCreateWithFlags(&evJoin, cudaEventDisableTiming);

    cudaEventRecord(evFork, 0);
    cudaStreamWaitEvent(s2, evFork, 0);
    zero_deg_kernel<<<(NN + 255) / 256, 256, 0, s2>>>();
    hist_kernel<<<(EE + 255) / 256, 256, 0, s2>>>(dst);
    scan_kernel<<<1, 512, 0, s2>>>();
    scatter_kernel<<<(EE + 255) / 256, 256, 0, s2>>>(src, dst);
    cudaEventRecord(evJoin, s2);

    // main stream: conversions (convB also resets elmax) + layer-0 GEMM
    convB_kernel<<<((128 + 512) * HD + 255) / 256, 256>>>(W0, W1, W2);
    convA_kernel<<<(NN * 128 / 4 + 255) / 256, 256>>>(x, NN * 128 / 4);

    dim3 ggrid(NN / 64, 2);

    gemm_mma_kernel<<<ggrid, 256, SMEM_GEMM>>>(af16, bf16, zb,
                                               emx + 0, al0, ar0, 128);
    cudaStreamWaitEvent(0, evJoin, 0);   // CSR ready before first agg
    agg_kernel<<<NN / 16, 256>>>(zb, nullptr, hA, emx + 0, 0, 1);

    // layer 1
    gemm_mma_kernel<<<ggrid, 256, SMEM_GEMM>>>(af16, bf16 + HD * HD, zb,
                                               emx + 4, al1, ar1, 256);
    agg_kernel<<<NN / 16, 256>>>(zb, hA, hB, emx + 4, 1, 1);

    // layer 2
    gemm_mma_kernel<<<ggrid, 256, SMEM_GEMM>>>(af16, bf16 + 2 * HD * HD, zb,
                                               emx + 8, al2, ar2, 256);
    agg_kernel<<<NN / 16, 256>>>(zb, hB, hA, emx + 8, 1, 0);

    pool_kernel<<<GG, 256>>>(hA, Wc, bc, out);
}